// round 1
// baseline (speedup 1.0000x reference)
#include <cuda_runtime.h>
#include <cuda_bf16.h>
#include <cstdint>

// Problem constants
#define BATCH 2
#define SEQ   2048
#define DMODEL 1024
#define HEADS 16
#define DHEAD 64
#define FFDIM 4096
#define ROWS  (BATCH*SEQ)   // 4096

// ---------------------------------------------------------------------------
// Scratch buffers (allocation-free: __device__ globals)
// ---------------------------------------------------------------------------
__device__ float g_q[BATCH*HEADS*SEQ*DHEAD];     // [B,H,S,Dh]
__device__ float g_k[BATCH*HEADS*SEQ*DHEAD];
__device__ float g_v[BATCH*HEADS*SEQ*DHEAD];
__device__ float g_att[ROWS*DMODEL];             // attention output, concat heads
__device__ float g_x1[ROWS*DMODEL];              // x + attn_out
__device__ float g_h[ROWS*FFDIM];                // relu(x1 W1^T + b1)

// ---------------------------------------------------------------------------
// Tiled SGEMM: C = A[M,Kd] * W[N,Kd]^T + bias, with epilogue variants.
//   MODE 0: plain           C[m,n] = v
//   MODE 1: qkv scatter     write v into [B,H,S,Dh] layout
//   MODE 2: residual add    C[m,n] = v + res[m,n]
//   MODE 3: relu            C[m,n] = max(v,0)
// BM=BN=128, BK=8, 256 threads, 8x8 microtile (4+4 split for LDS banking).
// M,N multiples of 128; Kd multiple of 8 (holds for all our shapes).
// ---------------------------------------------------------------------------
template<int MODE>
__global__ __launch_bounds__(256)
void gemm128(const float* __restrict__ A, const float* __restrict__ W,
             const float* __restrict__ bias, const float* __restrict__ res,
             float* __restrict__ C, int M, int N, int Kd)
{
    __shared__ float As[8][128];
    __shared__ float Ws[8][128];

    const int tid = threadIdx.x;
    const int m0 = blockIdx.y * 128;
    const int n0 = blockIdx.x * 128;

    const int lr = tid >> 1;          // 0..127 tile row
    const int lc = (tid & 1) * 4;     // 0 or 4 within BK

    const float* Ag = A + (size_t)(m0 + lr) * Kd + lc;
    const float* Wg = W + (size_t)(n0 + lr) * Kd + lc;

    const int ty = tid >> 4;          // 0..15
    const int tx = tid & 15;          // 0..15

    float acc[8][8];
    #pragma unroll
    for (int i = 0; i < 8; i++)
        #pragma unroll
        for (int j = 0; j < 8; j++) acc[i][j] = 0.f;

    for (int k0 = 0; k0 < Kd; k0 += 8) {
        float4 a4 = *(const float4*)(Ag + k0);
        float4 w4 = *(const float4*)(Wg + k0);
        __syncthreads();
        As[lc + 0][lr] = a4.x; As[lc + 1][lr] = a4.y;
        As[lc + 2][lr] = a4.z; As[lc + 3][lr] = a4.w;
        Ws[lc + 0][lr] = w4.x; Ws[lc + 1][lr] = w4.y;
        Ws[lc + 2][lr] = w4.z; Ws[lc + 3][lr] = w4.w;
        __syncthreads();

        #pragma unroll
        for (int kk = 0; kk < 8; kk++) {
            float4 a0 = *(const float4*)&As[kk][ty * 4];
            float4 a1 = *(const float4*)&As[kk][ty * 4 + 64];
            float4 b0 = *(const float4*)&Ws[kk][tx * 4];
            float4 b1 = *(const float4*)&Ws[kk][tx * 4 + 64];
            float ra[8] = {a0.x, a0.y, a0.z, a0.w, a1.x, a1.y, a1.z, a1.w};
            float rb[8] = {b0.x, b0.y, b0.z, b0.w, b1.x, b1.y, b1.z, b1.w};
            #pragma unroll
            for (int i = 0; i < 8; i++)
                #pragma unroll
                for (int j = 0; j < 8; j++)
                    acc[i][j] = fmaf(ra[i], rb[j], acc[i][j]);
        }
    }

    #pragma unroll
    for (int i = 0; i < 8; i++) {
        const int m = m0 + ((i < 4) ? (ty * 4 + i) : (64 + ty * 4 + i - 4));
        #pragma unroll
        for (int j = 0; j < 8; j++) {
            const int n = n0 + ((j < 4) ? (tx * 4 + j) : (64 + tx * 4 + j - 4));
            float v = acc[i][j] + bias[n];
            const size_t idx = (size_t)m * N + n;
            if (MODE == 0) {
                C[idx] = v;
            } else if (MODE == 1) {
                // m -> (b,s), n -> (h,k); dst layout [B,H,S,Dh]
                const size_t d = (((size_t)(m >> 11) * HEADS + (n >> 6)) * SEQ
                                  + (m & 2047)) * DHEAD + (n & 63);
                C[d] = v;
            } else if (MODE == 2) {
                C[idx] = v + res[idx];
            } else {
                C[idx] = fmaxf(v, 0.f);
            }
        }
    }
}

// ---------------------------------------------------------------------------
// Causal flash attention, fp32. One block = 128 query rows of one (b,h).
// Each thread owns one query row; q and o accumulator in registers (float4x16),
// K/V tiles (64 keys) staged in shared (float4 with +1 pad).
// ---------------------------------------------------------------------------
__global__ __launch_bounds__(128)
void flash_attn(const float* __restrict__ Q, const float* __restrict__ Kg,
                const float* __restrict__ Vg, float* __restrict__ Out)
{
    __shared__ float4 Ks4[64][17];
    __shared__ float4 Vs4[64][17];

    const int bh = blockIdx.y;               // 0..31
    const int b  = bh >> 4;
    const int h  = bh & 15;
    const int q0 = blockIdx.x * 128;
    const int qrow = q0 + threadIdx.x;       // global query index within head

    // load q row into registers
    float4 q4[16];
    {
        const float4* qp = (const float4*)(Q + ((size_t)bh * SEQ + qrow) * DHEAD);
        #pragma unroll
        for (int dd = 0; dd < 16; dd++) q4[dd] = qp[dd];
    }

    float m_i = -INFINITY, l_i = 0.f;
    float4 o4[16];
    #pragma unroll
    for (int dd = 0; dd < 16; dd++) o4[dd] = make_float4(0.f, 0.f, 0.f, 0.f);

    const float scale = 0.125f;              // 1/sqrt(64)
    const int numT = blockIdx.x * 2 + 2;     // tiles of 64 covering [0, q0+128)

    for (int t = 0; t < numT; t++) {
        const int j0 = t * 64;
        // stage K/V tile
        {
            const float* kb = Kg + ((size_t)bh * SEQ + j0) * DHEAD;
            const float* vb = Vg + ((size_t)bh * SEQ + j0) * DHEAD;
            #pragma unroll
            for (int i = 0; i < 8; i++) {
                const int idx = threadIdx.x + i * 128;   // 0..1023
                const int r = idx >> 4;
                const int c = idx & 15;
                Ks4[r][c] = *(const float4*)(kb + r * DHEAD + c * 4);
                Vs4[r][c] = *(const float4*)(vb + r * DHEAD + c * 4);
            }
        }
        __syncthreads();

        for (int jc = 0; jc < 64; jc += 16) {
            if (j0 + jc > qrow) break;       // fully-masked chunk (first chunk always valid)
            float p[16];
            float tmax = -INFINITY;
            #pragma unroll
            for (int u = 0; u < 16; u++) {
                const int jg = j0 + jc + u;
                float s = 0.f;
                #pragma unroll
                for (int dd = 0; dd < 16; dd++) {
                    float4 kv = Ks4[jc + u][dd];
                    s = fmaf(q4[dd].x, kv.x, s);
                    s = fmaf(q4[dd].y, kv.y, s);
                    s = fmaf(q4[dd].z, kv.z, s);
                    s = fmaf(q4[dd].w, kv.w, s);
                }
                p[u] = (jg <= qrow) ? s * scale : -INFINITY;
                tmax = fmaxf(tmax, p[u]);
            }
            const float mnew = fmaxf(m_i, tmax);
            const float alpha = __expf(m_i - mnew);      // first iter: exp(-inf)=0
            l_i *= alpha;
            #pragma unroll
            for (int dd = 0; dd < 16; dd++) {
                o4[dd].x *= alpha; o4[dd].y *= alpha;
                o4[dd].z *= alpha; o4[dd].w *= alpha;
            }
            #pragma unroll
            for (int u = 0; u < 16; u++) {
                const float pe = __expf(p[u] - mnew);    // masked -> 0
                l_i += pe;
                #pragma unroll
                for (int dd = 0; dd < 16; dd++) {
                    float4 vv = Vs4[jc + u][dd];
                    o4[dd].x = fmaf(pe, vv.x, o4[dd].x);
                    o4[dd].y = fmaf(pe, vv.y, o4[dd].y);
                    o4[dd].z = fmaf(pe, vv.z, o4[dd].z);
                    o4[dd].w = fmaf(pe, vv.w, o4[dd].w);
                }
            }
            m_i = mnew;
        }
        __syncthreads();
    }

    const float inv = 1.f / l_i;
    float4* op = (float4*)(Out + ((size_t)b * SEQ + qrow) * DMODEL + h * DHEAD);
    #pragma unroll
    for (int dd = 0; dd < 16; dd++) {
        float4 r = o4[dd];
        r.x *= inv; r.y *= inv; r.z *= inv; r.w *= inv;
        op[dd] = r;
    }
}

// ---------------------------------------------------------------------------
// Launch
// ---------------------------------------------------------------------------
extern "C" void kernel_launch(void* const* d_in, const int* in_sizes, int n_in,
                              void* d_out, int out_size)
{
    const float* x  = (const float*)d_in[0];
    const float* Wq = (const float*)d_in[1];
    const float* bq = (const float*)d_in[2];
    const float* Wk = (const float*)d_in[3];
    const float* bk = (const float*)d_in[4];
    const float* Wv = (const float*)d_in[5];
    const float* bv = (const float*)d_in[6];
    const float* Wo = (const float*)d_in[7];
    const float* bo = (const float*)d_in[8];
    const float* W1 = (const float*)d_in[9];
    const float* b1 = (const float*)d_in[10];
    const float* W2 = (const float*)d_in[11];
    const float* b2 = (const float*)d_in[12];
    float* out = (float*)d_out;

    float *pq, *pk, *pv, *patt, *px1, *ph;
    cudaGetSymbolAddress((void**)&pq,  g_q);
    cudaGetSymbolAddress((void**)&pk,  g_k);
    cudaGetSymbolAddress((void**)&pv,  g_v);
    cudaGetSymbolAddress((void**)&patt, g_att);
    cudaGetSymbolAddress((void**)&px1, g_x1);
    cudaGetSymbolAddress((void**)&ph,  g_h);

    const dim3 blk(256);
    const dim3 g_proj(DMODEL / 128, ROWS / 128);   // (8, 32)
    const dim3 g_ffn1(FFDIM / 128, ROWS / 128);    // (32, 32)

    // QKV projections -> [B,H,S,Dh]
    gemm128<1><<<g_proj, blk>>>(x, Wq, bq, nullptr, pq, ROWS, DMODEL, DMODEL);
    gemm128<1><<<g_proj, blk>>>(x, Wk, bk, nullptr, pk, ROWS, DMODEL, DMODEL);
    gemm128<1><<<g_proj, blk>>>(x, Wv, bv, nullptr, pv, ROWS, DMODEL, DMODEL);

    // causal attention
    flash_attn<<<dim3(SEQ / 128, BATCH * HEADS), 128>>>(pq, pk, pv, patt);

    // output projection + residual: x1 = att*Wo^T + bo + x
    gemm128<2><<<g_proj, blk>>>(patt, Wo, bo, x, px1, ROWS, DMODEL, DMODEL);

    // FFN
    gemm128<3><<<g_ffn1, blk>>>(px1, W1, b1, nullptr, ph, ROWS, FFDIM, DMODEL);
    gemm128<2><<<g_proj, blk>>>(ph, W2, b2, px1, out, ROWS, DMODEL, FFDIM);
}

// round 3
// speedup vs baseline: 1.5555x; 1.5555x over previous
#include <cuda_runtime.h>
#include <cuda_bf16.h>
#include <cstdint>

// Problem constants
#define BATCH 2
#define SEQ   2048
#define DMODEL 1024
#define HEADS 16
#define DHEAD 64
#define FFDIM 4096
#define ROWS  (BATCH*SEQ)   // 4096

// ===========================================================================
// Scratch (allocation-free: __device__ globals)
// ===========================================================================
__device__ __nv_bfloat16 g_x_hi[ROWS*DMODEL],   g_x_lo[ROWS*DMODEL];
__device__ __nv_bfloat16 g_wqkv_hi[3*DMODEL*DMODEL], g_wqkv_lo[3*DMODEL*DMODEL];
__device__ __nv_bfloat16 g_wo_hi[DMODEL*DMODEL], g_wo_lo[DMODEL*DMODEL];
__device__ __nv_bfloat16 g_w1_hi[FFDIM*DMODEL],  g_w1_lo[FFDIM*DMODEL];
__device__ __nv_bfloat16 g_w2_hi[DMODEL*FFDIM],  g_w2_lo[DMODEL*FFDIM];
__device__ float g_q[BATCH*HEADS*SEQ*DHEAD];
__device__ float g_k[BATCH*HEADS*SEQ*DHEAD];
__device__ float g_v[BATCH*HEADS*SEQ*DHEAD];
__device__ __nv_bfloat16 g_att_hi[ROWS*DMODEL],  g_att_lo[ROWS*DMODEL];
__device__ float g_x1[ROWS*DMODEL];
__device__ __nv_bfloat16 g_x1_hi[ROWS*DMODEL],   g_x1_lo[ROWS*DMODEL];
__device__ __nv_bfloat16 g_h_hi[ROWS*FFDIM],     g_h_lo[ROWS*FFDIM];

// ===========================================================================
// Helpers
// ===========================================================================
__device__ __forceinline__ uint32_t smem_u32(const void* p) {
    uint32_t a;
    asm("{ .reg .u64 t; cvta.to.shared.u64 t, %1; cvt.u32.u64 %0, t; }" : "=r"(a) : "l"(p));
    return a;
}
#define CP_ASYNC16(dst_u32, src_ptr) \
    asm volatile("cp.async.cg.shared.global [%0], [%1], 16;" :: "r"(dst_u32), "l"(src_ptr) : "memory")
#define CP_COMMIT() asm volatile("cp.async.commit_group;" ::: "memory")
#define CP_WAIT2()  asm volatile("cp.async.wait_group 2;" ::: "memory")
#define LDSM4(r0,r1,r2,r3,addr) \
    asm volatile("ldmatrix.sync.aligned.m8n8.x4.shared.b16 {%0,%1,%2,%3}, [%4];" \
        : "=r"(r0), "=r"(r1), "=r"(r2), "=r"(r3) : "r"(addr))
__device__ __forceinline__ void mma_bf16(float* d, const uint32_t* a, const uint32_t* b) {
    asm volatile("mma.sync.aligned.m16n8k16.row.col.f32.bf16.bf16.f32 "
        "{%0,%1,%2,%3}, {%4,%5,%6,%7}, {%8,%9}, {%0,%1,%2,%3};"
        : "+f"(d[0]), "+f"(d[1]), "+f"(d[2]), "+f"(d[3])
        : "r"(a[0]), "r"(a[1]), "r"(a[2]), "r"(a[3]), "r"(b[0]), "r"(b[1]));
}
__device__ __forceinline__ void store_hilo(__nv_bfloat16* hi, __nv_bfloat16* lo,
                                           size_t idx, float a, float b) {
    __nv_bfloat16 ha = __float2bfloat16(a), hb = __float2bfloat16(b);
    __nv_bfloat162 hp; hp.x = ha; hp.y = hb;
    __nv_bfloat162 lp;
    lp.x = __float2bfloat16(a - __bfloat162float(ha));
    lp.y = __float2bfloat16(b - __bfloat162float(hb));
    *(__nv_bfloat162*)(hi + idx) = hp;
    *(__nv_bfloat162*)(lo + idx) = lp;
}

// ===========================================================================
// fp32 -> (bf16 hi, bf16 lo) split
// ===========================================================================
__global__ void split_f32(const float* __restrict__ in, __nv_bfloat16* __restrict__ hi,
                          __nv_bfloat16* __restrict__ lo, int n4) {
    int i = blockIdx.x * blockDim.x + threadIdx.x;
    if (i >= n4) return;
    float4 v = ((const float4*)in)[i];
    store_hilo(hi, lo, (size_t)i * 4,     v.x, v.y);
    store_hilo(hi, lo, (size_t)i * 4 + 2, v.z, v.w);
}

// ===========================================================================
// Split-bf16 GEMM via mma.sync: C[M,N] = A[M,K] * W[N,K]^T (+ bias, epilogue)
//   MODE 0: QKV combined (N=3072) -> scatter fp32 into q/k/v [B,H,S,Dh]
//   MODE 1: Wo: +res(x) -> x1 fp32 AND x1 hi/lo
//   MODE 2: FFN1: relu  -> h hi/lo
//   MODE 3: FFN2: +res(x1) -> out fp32
// Block tile 128x256, BK=32, 8 warps (2x4), warp tile 64x64, 3-stage cp.async.
// Smem rows padded to 80B (ldmatrix conflict-free).
// ===========================================================================
#define BK 32
#define ROWB 80                               // bytes per smem row (32 bf16 + pad)
#define A_TILE (128 * ROWB)                   // 10240
#define W_TILE (256 * ROWB)                   // 20480
#define STAGE_B (2 * A_TILE + 2 * W_TILE)     // 61440
#define NSTAGE 3
#define GEMM_SMEM (NSTAGE * STAGE_B)          // 184320

template<int MODE>
__global__ void __launch_bounds__(256, 1) tc_gemm(
    const __nv_bfloat16* __restrict__ Ahi, const __nv_bfloat16* __restrict__ Alo,
    const __nv_bfloat16* __restrict__ Whi, const __nv_bfloat16* __restrict__ Wlo,
    const float* __restrict__ bias0, const float* __restrict__ bias1, const float* __restrict__ bias2,
    const float* __restrict__ res,
    float* __restrict__ of0, float* __restrict__ of1, float* __restrict__ of2,
    __nv_bfloat16* __restrict__ ohi, __nv_bfloat16* __restrict__ olo,
    int M, int N, int K)
{
    extern __shared__ char smem[];
    const uint32_t sb = smem_u32(smem);
    const int tid = threadIdx.x;
    const int wid = tid >> 5;
    const int lane = tid & 31;
    const int wm = wid >> 2;          // 0..1 (M)
    const int wn = wid & 3;           // 0..3 (N)
    const int m0 = blockIdx.y * 128;
    const int n0 = blockIdx.x * 256;

    const int nc = K / BK;

    // ---- async loader: 12 x 16B per thread per chunk ----
    auto load_chunk = [&](int c, int s) {
        const uint32_t stage = sb + s * STAGE_B;
        const int kbase = c * BK;
        #pragma unroll
        for (int i = 0; i < 12; i++) {
            const int u = tid + 256 * i;             // 0..3071
            if (u < 1024) {                          // A tiles
                const int t = u >> 9;                // 0=hi 1=lo
                const int r = (u >> 2) & 127;
                const int kc = u & 3;
                const uint32_t dst = stage + t * A_TILE + r * ROWB + kc * 16;
                const __nv_bfloat16* src = (t == 0 ? Ahi : Alo)
                    + (size_t)(m0 + r) * K + kbase + kc * 8;
                CP_ASYNC16(dst, src);
            } else {                                 // W tiles
                const int v = u - 1024;
                const int t = v >> 10;               // 0=hi 1=lo
                const int r = (v >> 2) & 255;
                const int kc = v & 3;
                const uint32_t dst = stage + 2 * A_TILE + t * W_TILE + r * ROWB + kc * 16;
                const __nv_bfloat16* src = (t == 0 ? Whi : Wlo)
                    + (size_t)(n0 + r) * K + kbase + kc * 8;
                CP_ASYNC16(dst, src);
            }
        }
    };

    float d[4][8][4];
    #pragma unroll
    for (int i = 0; i < 4; i++)
        #pragma unroll
        for (int j = 0; j < 8; j++)
            #pragma unroll
            for (int e = 0; e < 4; e++) d[i][j][e] = 0.f;

    // preload stages 0,1
    load_chunk(0, 0); CP_COMMIT();
    load_chunk(1, 1); CP_COMMIT();

    const int lr = lane & 15;
    const int lh = lane >> 4;

    for (int c = 0; c < nc; c++) {
        if (c + 2 < nc) load_chunk(c + 2, (c + 2) % NSTAGE);
        CP_COMMIT();            // commit every iter -> uniform group counting
        CP_WAIT2();             // chunk c resident
        __syncthreads();

        const uint32_t stage = sb + (c % NSTAGE) * STAGE_B;
        const uint32_t sA = stage;
        const uint32_t sW = stage + 2 * A_TILE;

        #pragma unroll
        for (int kk = 0; kk < BK; kk += 16) {
            const uint32_t colb = (kk + lh * 8) * 2;
            uint32_t ah[4][4], al[4][4];
            #pragma unroll
            for (int mi = 0; mi < 4; mi++) {
                const uint32_t rowo = (wm * 64 + mi * 16 + lr) * ROWB + colb;
                LDSM4(ah[mi][0], ah[mi][1], ah[mi][2], ah[mi][3], sA + rowo);
                LDSM4(al[mi][0], al[mi][1], al[mi][2], al[mi][3], sA + A_TILE + rowo);
            }
            uint32_t bh[8][2], bl[8][2];
            #pragma unroll
            for (int p = 0; p < 4; p++) {
                const uint32_t rowo = (wn * 64 + p * 16 + lr) * ROWB + colb;
                uint32_t r0, r1, r2, r3;
                LDSM4(r0, r1, r2, r3, sW + rowo);
                bh[2*p][0] = r0; bh[2*p][1] = r2;
                bh[2*p+1][0] = r1; bh[2*p+1][1] = r3;
                LDSM4(r0, r1, r2, r3, sW + W_TILE + rowo);
                bl[2*p][0] = r0; bl[2*p][1] = r2;
                bl[2*p+1][0] = r1; bl[2*p+1][1] = r3;
            }
            #pragma unroll
            for (int mi = 0; mi < 4; mi++)
                #pragma unroll
                for (int nj = 0; nj < 8; nj++) {
                    mma_bf16(d[mi][nj], ah[mi], bh[nj]);
                    mma_bf16(d[mi][nj], ah[mi], bl[nj]);
                    mma_bf16(d[mi][nj], al[mi], bh[nj]);
                }
        }
        __syncthreads();
    }

    // ---- epilogue (register fragments -> gmem) ----
    const int g = lane >> 2;
    const int t2 = (lane & 3) * 2;

    #pragma unroll
    for (int mi = 0; mi < 4; mi++) {
        const int m = m0 + wm * 64 + mi * 16 + g;      // and m+8
        #pragma unroll
        for (int nj = 0; nj < 8; nj++) {
            const int n = n0 + wn * 64 + nj * 8 + t2;
            float c0 = d[mi][nj][0], c1 = d[mi][nj][1];
            float c2 = d[mi][nj][2], c3 = d[mi][nj][3];

            if (MODE == 0) {
                const int which = n >> 10;             // uniform per block
                const int nn = n & 1023;
                const float* bp = (which == 0) ? bias0 : (which == 1) ? bias1 : bias2;
                const float bx = bp[nn], by = bp[nn + 1];
                float* dst = (which == 0) ? of0 : (which == 1) ? of1 : of2;
                const int h = nn >> 6, dh = nn & 63;
                const int b = m >> 11, s_ = m & 2047;
                float2* p0 = (float2*)(dst + (((size_t)b * HEADS + h) * SEQ + s_) * DHEAD + dh);
                float2* p1 = (float2*)(dst + (((size_t)b * HEADS + h) * SEQ + s_ + 8) * DHEAD + dh);
                *p0 = make_float2(c0 + bx, c1 + by);
                *p1 = make_float2(c2 + bx, c3 + by);
            } else {
                const float bx = bias0[n], by = bias0[n + 1];
                const size_t i0 = (size_t)m * N + n;
                const size_t i1 = (size_t)(m + 8) * N + n;
                float v00 = c0 + bx, v01 = c1 + by;
                float v10 = c2 + bx, v11 = c3 + by;
                if (MODE == 1 || MODE == 3) {
                    const float2 r0 = *(const float2*)(res + i0);
                    const float2 r1 = *(const float2*)(res + i1);
                    v00 += r0.x; v01 += r0.y; v10 += r1.x; v11 += r1.y;
                }
                if (MODE == 2) {
                    v00 = fmaxf(v00, 0.f); v01 = fmaxf(v01, 0.f);
                    v10 = fmaxf(v10, 0.f); v11 = fmaxf(v11, 0.f);
                }
                if (MODE == 1 || MODE == 3) {
                    *(float2*)(of0 + i0) = make_float2(v00, v01);
                    *(float2*)(of0 + i1) = make_float2(v10, v11);
                }
                if (MODE == 1 || MODE == 2) {
                    store_hilo(ohi, olo, i0, v00, v01);
                    store_hilo(ohi, olo, i1, v10, v11);
                }
            }
        }
    }
}

// ===========================================================================
// Causal flash attention, fp32 in, bf16 hi/lo out (verified R1 math).
// ===========================================================================
__global__ __launch_bounds__(128)
void flash_attn(const float* __restrict__ Q, const float* __restrict__ Kg,
                const float* __restrict__ Vg,
                __nv_bfloat16* __restrict__ Ohi, __nv_bfloat16* __restrict__ Olo)
{
    __shared__ float4 Ks4[64][17];
    __shared__ float4 Vs4[64][17];

    const int bh = blockIdx.y;
    const int b  = bh >> 4;
    const int h  = bh & 15;
    const int q0 = blockIdx.x * 128;
    const int qrow = q0 + threadIdx.x;

    float4 q4[16];
    {
        const float4* qp = (const float4*)(Q + ((size_t)bh * SEQ + qrow) * DHEAD);
        #pragma unroll
        for (int dd = 0; dd < 16; dd++) q4[dd] = qp[dd];
    }

    float m_i = -INFINITY, l_i = 0.f;
    float4 o4[16];
    #pragma unroll
    for (int dd = 0; dd < 16; dd++) o4[dd] = make_float4(0.f, 0.f, 0.f, 0.f);

    const float scale = 0.125f;
    const int numT = blockIdx.x * 2 + 2;

    for (int t = 0; t < numT; t++) {
        const int j0 = t * 64;
        {
            const float* kb = Kg + ((size_t)bh * SEQ + j0) * DHEAD;
            const float* vb = Vg + ((size_t)bh * SEQ + j0) * DHEAD;
            #pragma unroll
            for (int i = 0; i < 8; i++) {
                const int idx = threadIdx.x + i * 128;
                const int r = idx >> 4, c = idx & 15;
                Ks4[r][c] = *(const float4*)(kb + r * DHEAD + c * 4);
                Vs4[r][c] = *(const float4*)(vb + r * DHEAD + c * 4);
            }
        }
        __syncthreads();

        for (int jc = 0; jc < 64; jc += 16) {
            if (j0 + jc > qrow) break;
            float p[16];
            float tmax = -INFINITY;
            #pragma unroll
            for (int u = 0; u < 16; u++) {
                const int jg = j0 + jc + u;
                float s = 0.f;
                #pragma unroll
                for (int dd = 0; dd < 16; dd++) {
                    float4 kv = Ks4[jc + u][dd];
                    s = fmaf(q4[dd].x, kv.x, s);
                    s = fmaf(q4[dd].y, kv.y, s);
                    s = fmaf(q4[dd].z, kv.z, s);
                    s = fmaf(q4[dd].w, kv.w, s);
                }
                p[u] = (jg <= qrow) ? s * scale : -INFINITY;
                tmax = fmaxf(tmax, p[u]);
            }
            const float mnew = fmaxf(m_i, tmax);
            const float alpha = __expf(m_i - mnew);
            l_i *= alpha;
            #pragma unroll
            for (int dd = 0; dd < 16; dd++) {
                o4[dd].x *= alpha; o4[dd].y *= alpha;
                o4[dd].z *= alpha; o4[dd].w *= alpha;
            }
            #pragma unroll
            for (int u = 0; u < 16; u++) {
                const float pe = __expf(p[u] - mnew);
                l_i += pe;
                #pragma unroll
                for (int dd = 0; dd < 16; dd++) {
                    float4 vv = Vs4[jc + u][dd];
                    o4[dd].x = fmaf(pe, vv.x, o4[dd].x);
                    o4[dd].y = fmaf(pe, vv.y, o4[dd].y);
                    o4[dd].z = fmaf(pe, vv.z, o4[dd].z);
                    o4[dd].w = fmaf(pe, vv.w, o4[dd].w);
                }
            }
            m_i = mnew;
        }
        __syncthreads();
    }

    const float inv = 1.f / l_i;
    const size_t ro = ((size_t)b * SEQ + qrow) * DMODEL + h * DHEAD;
    #pragma unroll
    for (int dd = 0; dd < 16; dd++) {
        float4 r = o4[dd];
        r.x *= inv; r.y *= inv; r.z *= inv; r.w *= inv;
        store_hilo(Ohi, Olo, ro + dd * 4,     r.x, r.y);
        store_hilo(Ohi, Olo, ro + dd * 4 + 2, r.z, r.w);
    }
}

// ===========================================================================
// Launch
// ===========================================================================
extern "C" void kernel_launch(void* const* d_in, const int* in_sizes, int n_in,
                              void* d_out, int out_size)
{
    const float* x  = (const float*)d_in[0];
    const float* Wq = (const float*)d_in[1];
    const float* bq = (const float*)d_in[2];
    const float* Wk = (const float*)d_in[3];
    const float* bk = (const float*)d_in[4];
    const float* Wv = (const float*)d_in[5];
    const float* bv = (const float*)d_in[6];
    const float* Wo = (const float*)d_in[7];
    const float* bo = (const float*)d_in[8];
    const float* W1 = (const float*)d_in[9];
    const float* b1 = (const float*)d_in[10];
    const float* W2 = (const float*)d_in[11];
    const float* b2 = (const float*)d_in[12];
    float* out = (float*)d_out;

    __nv_bfloat16 *xh, *xl, *wqkvh, *wqkvl, *woh, *wol, *w1h, *w1l, *w2h, *w2l;
    __nv_bfloat16 *atth, *attl, *x1h, *x1l, *hh, *hl;
    float *pq, *pk, *pv, *px1;
    cudaGetSymbolAddress((void**)&xh, g_x_hi);       cudaGetSymbolAddress((void**)&xl, g_x_lo);
    cudaGetSymbolAddress((void**)&wqkvh, g_wqkv_hi); cudaGetSymbolAddress((void**)&wqkvl, g_wqkv_lo);
    cudaGetSymbolAddress((void**)&woh, g_wo_hi);     cudaGetSymbolAddress((void**)&wol, g_wo_lo);
    cudaGetSymbolAddress((void**)&w1h, g_w1_hi);     cudaGetSymbolAddress((void**)&w1l, g_w1_lo);
    cudaGetSymbolAddress((void**)&w2h, g_w2_hi);     cudaGetSymbolAddress((void**)&w2l, g_w2_lo);
    cudaGetSymbolAddress((void**)&atth, g_att_hi);   cudaGetSymbolAddress((void**)&attl, g_att_lo);
    cudaGetSymbolAddress((void**)&x1h, g_x1_hi);     cudaGetSymbolAddress((void**)&x1l, g_x1_lo);
    cudaGetSymbolAddress((void**)&hh, g_h_hi);       cudaGetSymbolAddress((void**)&hl, g_h_lo);
    cudaGetSymbolAddress((void**)&pq, g_q);          cudaGetSymbolAddress((void**)&pk, g_k);
    cudaGetSymbolAddress((void**)&pv, g_v);          cudaGetSymbolAddress((void**)&px1, g_x1);

    cudaFuncSetAttribute(tc_gemm<0>, cudaFuncAttributeMaxDynamicSharedMemorySize, GEMM_SMEM);
    cudaFuncSetAttribute(tc_gemm<1>, cudaFuncAttributeMaxDynamicSharedMemorySize, GEMM_SMEM);
    cudaFuncSetAttribute(tc_gemm<2>, cudaFuncAttributeMaxDynamicSharedMemorySize, GEMM_SMEM);
    cudaFuncSetAttribute(tc_gemm<3>, cudaFuncAttributeMaxDynamicSharedMemorySize, GEMM_SMEM);

    // --- split fp32 -> bf16 hi/lo ---
    const int T = 256;
    split_f32<<<(ROWS*DMODEL/4 + T-1)/T, T>>>(x,  xh, xl, ROWS*DMODEL/4);
    split_f32<<<(DMODEL*DMODEL/4 + T-1)/T, T>>>(Wq, wqkvh,                   wqkvl,                   DMODEL*DMODEL/4);
    split_f32<<<(DMODEL*DMODEL/4 + T-1)/T, T>>>(Wk, wqkvh + DMODEL*DMODEL,   wqkvl + DMODEL*DMODEL,   DMODEL*DMODEL/4);
    split_f32<<<(DMODEL*DMODEL/4 + T-1)/T, T>>>(Wv, wqkvh + 2*DMODEL*DMODEL, wqkvl + 2*DMODEL*DMODEL, DMODEL*DMODEL/4);
    split_f32<<<(DMODEL*DMODEL/4 + T-1)/T, T>>>(Wo, woh, wol, DMODEL*DMODEL/4);
    split_f32<<<(FFDIM*DMODEL/4 + T-1)/T, T>>>(W1, w1h, w1l, FFDIM*DMODEL/4);
    split_f32<<<(DMODEL*FFDIM/4 + T-1)/T, T>>>(W2, w2h, w2l, DMODEL*FFDIM/4);

    const dim3 blk(256);

    // QKV combined: [4096,3072] -> scatter q/k/v [B,H,S,Dh]
    tc_gemm<0><<<dim3(3*DMODEL/256, ROWS/128), blk, GEMM_SMEM>>>(
        xh, xl, wqkvh, wqkvl, bq, bk, bv, nullptr,
        pq, pk, pv, nullptr, nullptr, ROWS, 3*DMODEL, DMODEL);

    // attention
    flash_attn<<<dim3(SEQ/128, BATCH*HEADS), 128>>>(pq, pk, pv, atth, attl);

    // x1 = att*Wo^T + bo + x  (fp32 + hi/lo)
    tc_gemm<1><<<dim3(DMODEL/256, ROWS/128), blk, GEMM_SMEM>>>(
        atth, attl, woh, wol, bo, nullptr, nullptr, x,
        px1, nullptr, nullptr, x1h, x1l, ROWS, DMODEL, DMODEL);

    // h = relu(x1*W1^T + b1)  (hi/lo)
    tc_gemm<2><<<dim3(FFDIM/256, ROWS/128), blk, GEMM_SMEM>>>(
        x1h, x1l, w1h, w1l, b1, nullptr, nullptr, nullptr,
        nullptr, nullptr, nullptr, hh, hl, ROWS, FFDIM, DMODEL);

    // out = h*W2^T + b2 + x1  (fp32)
    tc_gemm<3><<<dim3(DMODEL/256, ROWS/128), blk, GEMM_SMEM>>>(
        hh, hl, w2h, w2l, b2, nullptr, nullptr, px1,
        out, nullptr, nullptr, nullptr, nullptr, ROWS, DMODEL, FFDIM);
}

// round 4
// speedup vs baseline: 2.4610x; 1.5821x over previous
#include <cuda_runtime.h>
#include <cuda_bf16.h>
#include <cstdint>

// Problem constants
#define BATCH 2
#define SEQ   2048
#define DMODEL 1024
#define HEADS 16
#define DHEAD 64
#define FFDIM 4096
#define ROWS  (BATCH*SEQ)   // 4096

// ===========================================================================
// Scratch (allocation-free: __device__ globals)
// ===========================================================================
__device__ __nv_bfloat16 g_x_hi[ROWS*DMODEL],   g_x_lo[ROWS*DMODEL];
__device__ __nv_bfloat16 g_wqkv_hi[3*DMODEL*DMODEL], g_wqkv_lo[3*DMODEL*DMODEL];
__device__ __nv_bfloat16 g_wo_hi[DMODEL*DMODEL], g_wo_lo[DMODEL*DMODEL];
__device__ __nv_bfloat16 g_w1_hi[FFDIM*DMODEL],  g_w1_lo[FFDIM*DMODEL];
__device__ __nv_bfloat16 g_w2_hi[DMODEL*FFDIM],  g_w2_lo[DMODEL*FFDIM];
__device__ __nv_bfloat16 g_q_hi[BATCH*HEADS*SEQ*DHEAD], g_q_lo[BATCH*HEADS*SEQ*DHEAD];
__device__ __nv_bfloat16 g_k_hi[BATCH*HEADS*SEQ*DHEAD], g_k_lo[BATCH*HEADS*SEQ*DHEAD];
__device__ __nv_bfloat16 g_v_hi[BATCH*HEADS*SEQ*DHEAD], g_v_lo[BATCH*HEADS*SEQ*DHEAD];
__device__ __nv_bfloat16 g_att_hi[ROWS*DMODEL],  g_att_lo[ROWS*DMODEL];
__device__ float g_x1[ROWS*DMODEL];
__device__ __nv_bfloat16 g_x1_hi[ROWS*DMODEL],   g_x1_lo[ROWS*DMODEL];
__device__ __nv_bfloat16 g_h_hi[ROWS*FFDIM],     g_h_lo[ROWS*FFDIM];

// ===========================================================================
// Helpers
// ===========================================================================
__device__ __forceinline__ uint32_t smem_u32(const void* p) {
    uint32_t a;
    asm("{ .reg .u64 t; cvta.to.shared.u64 t, %1; cvt.u32.u64 %0, t; }" : "=r"(a) : "l"(p));
    return a;
}
#define CP_ASYNC16(dst_u32, src_ptr) \
    asm volatile("cp.async.cg.shared.global [%0], [%1], 16;" :: "r"(dst_u32), "l"(src_ptr) : "memory")
#define CP_COMMIT() asm volatile("cp.async.commit_group;" ::: "memory")
#define CP_WAIT0()  asm volatile("cp.async.wait_group 0;" ::: "memory")
#define CP_WAIT1()  asm volatile("cp.async.wait_group 1;" ::: "memory")
#define CP_WAIT2()  asm volatile("cp.async.wait_group 2;" ::: "memory")
#define LDSM4(r0,r1,r2,r3,addr) \
    asm volatile("ldmatrix.sync.aligned.m8n8.x4.shared.b16 {%0,%1,%2,%3}, [%4];" \
        : "=r"(r0), "=r"(r1), "=r"(r2), "=r"(r3) : "r"(addr))
#define LDSM4T(r0,r1,r2,r3,addr) \
    asm volatile("ldmatrix.sync.aligned.m8n8.x4.trans.shared.b16 {%0,%1,%2,%3}, [%4];" \
        : "=r"(r0), "=r"(r1), "=r"(r2), "=r"(r3) : "r"(addr))
__device__ __forceinline__ void mma_bf16(float* d, const uint32_t* a, const uint32_t* b) {
    asm volatile("mma.sync.aligned.m16n8k16.row.col.f32.bf16.bf16.f32 "
        "{%0,%1,%2,%3}, {%4,%5,%6,%7}, {%8,%9}, {%0,%1,%2,%3};"
        : "+f"(d[0]), "+f"(d[1]), "+f"(d[2]), "+f"(d[3])
        : "r"(a[0]), "r"(a[1]), "r"(a[2]), "r"(a[3]), "r"(b[0]), "r"(b[1]));
}
__device__ __forceinline__ void store_hilo(__nv_bfloat16* hi, __nv_bfloat16* lo,
                                           size_t idx, float a, float b) {
    __nv_bfloat16 ha = __float2bfloat16(a), hb = __float2bfloat16(b);
    __nv_bfloat162 hp; hp.x = ha; hp.y = hb;
    __nv_bfloat162 lp;
    lp.x = __float2bfloat16(a - __bfloat162float(ha));
    lp.y = __float2bfloat16(b - __bfloat162float(hb));
    *(__nv_bfloat162*)(hi + idx) = hp;
    *(__nv_bfloat162*)(lo + idx) = lp;
}
__device__ __forceinline__ uint32_t packh_u32(float a, float b) {
    __nv_bfloat162 p = __floats2bfloat162_rn(a, b);   // .x = a (low half)
    return *reinterpret_cast<uint32_t*>(&p);
}
__device__ __forceinline__ uint32_t packl_u32(float a, float b, uint32_t hp_u32) {
    __nv_bfloat162 hp = *reinterpret_cast<__nv_bfloat162*>(&hp_u32);
    return packh_u32(a - __bfloat162float(hp.x), b - __bfloat162float(hp.y));
}

// ===========================================================================
// fp32 -> (bf16 hi, bf16 lo) split
// ===========================================================================
__global__ void split_f32(const float* __restrict__ in, __nv_bfloat16* __restrict__ hi,
                          __nv_bfloat16* __restrict__ lo, int n4) {
    int i = blockIdx.x * blockDim.x + threadIdx.x;
    if (i >= n4) return;
    float4 v = ((const float4*)in)[i];
    store_hilo(hi, lo, (size_t)i * 4,     v.x, v.y);
    store_hilo(hi, lo, (size_t)i * 4 + 2, v.z, v.w);
}

// ===========================================================================
// Split-bf16 GEMM via mma.sync: C[M,N] = A[M,K] * W[N,K]^T (+ bias, epilogue)
//   MODE 0: QKV combined (N=3072) -> q/k/v bf16 hi/lo [B,H,S,Dh] (q scaled 1/8)
//   MODE 1: Wo: +res(x) -> x1 fp32 AND x1 hi/lo
//   MODE 2: FFN1: relu  -> h hi/lo
//   MODE 3: FFN2: +res(x1) -> out fp32
// Block tile 128x256, BK=32, 8 warps (2x4), warp tile 64x64, 3-stage cp.async.
// ===========================================================================
#define BK 32
#define ROWB 80
#define A_TILE (128 * ROWB)
#define W_TILE (256 * ROWB)
#define STAGE_B (2 * A_TILE + 2 * W_TILE)
#define NSTAGE 3
#define GEMM_SMEM (NSTAGE * STAGE_B)

template<int MODE>
__global__ void __launch_bounds__(256, 1) tc_gemm(
    const __nv_bfloat16* __restrict__ Ahi, const __nv_bfloat16* __restrict__ Alo,
    const __nv_bfloat16* __restrict__ Whi, const __nv_bfloat16* __restrict__ Wlo,
    const float* __restrict__ bias0, const float* __restrict__ bias1, const float* __restrict__ bias2,
    const float* __restrict__ res,
    float* __restrict__ ofp,
    __nv_bfloat16* __restrict__ o0h, __nv_bfloat16* __restrict__ o0l,
    __nv_bfloat16* __restrict__ o1h, __nv_bfloat16* __restrict__ o1l,
    __nv_bfloat16* __restrict__ o2h, __nv_bfloat16* __restrict__ o2l,
    int M, int N, int K)
{
    extern __shared__ char smem[];
    const uint32_t sb = smem_u32(smem);
    const int tid = threadIdx.x;
    const int wid = tid >> 5;
    const int lane = tid & 31;
    const int wm = wid >> 2;
    const int wn = wid & 3;
    const int m0 = blockIdx.y * 128;
    const int n0 = blockIdx.x * 256;
    const int nc = K / BK;

    auto load_chunk = [&](int c, int s) {
        const uint32_t stage = sb + s * STAGE_B;
        const int kbase = c * BK;
        #pragma unroll
        for (int i = 0; i < 12; i++) {
            const int u = tid + 256 * i;
            if (u < 1024) {
                const int t = u >> 9;
                const int r = (u >> 2) & 127;
                const int kc = u & 3;
                const uint32_t dst = stage + t * A_TILE + r * ROWB + kc * 16;
                const __nv_bfloat16* src = (t == 0 ? Ahi : Alo)
                    + (size_t)(m0 + r) * K + kbase + kc * 8;
                CP_ASYNC16(dst, src);
            } else {
                const int v = u - 1024;
                const int t = v >> 10;
                const int r = (v >> 2) & 255;
                const int kc = v & 3;
                const uint32_t dst = stage + 2 * A_TILE + t * W_TILE + r * ROWB + kc * 16;
                const __nv_bfloat16* src = (t == 0 ? Whi : Wlo)
                    + (size_t)(n0 + r) * K + kbase + kc * 8;
                CP_ASYNC16(dst, src);
            }
        }
    };

    float d[4][8][4];
    #pragma unroll
    for (int i = 0; i < 4; i++)
        #pragma unroll
        for (int j = 0; j < 8; j++)
            #pragma unroll
            for (int e = 0; e < 4; e++) d[i][j][e] = 0.f;

    load_chunk(0, 0); CP_COMMIT();
    load_chunk(1, 1); CP_COMMIT();

    const int lr = lane & 15;
    const int lh = lane >> 4;

    for (int c = 0; c < nc; c++) {
        if (c + 2 < nc) load_chunk(c + 2, (c + 2) % NSTAGE);
        CP_COMMIT();
        CP_WAIT2();
        __syncthreads();

        const uint32_t stage = sb + (c % NSTAGE) * STAGE_B;
        const uint32_t sA = stage;
        const uint32_t sW = stage + 2 * A_TILE;

        #pragma unroll
        for (int kk = 0; kk < BK; kk += 16) {
            const uint32_t colb = (kk + lh * 8) * 2;
            uint32_t ah[4][4], al[4][4];
            #pragma unroll
            for (int mi = 0; mi < 4; mi++) {
                const uint32_t rowo = (wm * 64 + mi * 16 + lr) * ROWB + colb;
                LDSM4(ah[mi][0], ah[mi][1], ah[mi][2], ah[mi][3], sA + rowo);
                LDSM4(al[mi][0], al[mi][1], al[mi][2], al[mi][3], sA + A_TILE + rowo);
            }
            uint32_t bh[8][2], bl[8][2];
            #pragma unroll
            for (int p = 0; p < 4; p++) {
                const uint32_t rowo = (wn * 64 + p * 16 + lr) * ROWB + colb;
                uint32_t r0, r1, r2, r3;
                LDSM4(r0, r1, r2, r3, sW + rowo);
                bh[2*p][0] = r0; bh[2*p][1] = r2;
                bh[2*p+1][0] = r1; bh[2*p+1][1] = r3;
                LDSM4(r0, r1, r2, r3, sW + W_TILE + rowo);
                bl[2*p][0] = r0; bl[2*p][1] = r2;
                bl[2*p+1][0] = r1; bl[2*p+1][1] = r3;
            }
            #pragma unroll
            for (int mi = 0; mi < 4; mi++)
                #pragma unroll
                for (int nj = 0; nj < 8; nj++) {
                    mma_bf16(d[mi][nj], ah[mi], bh[nj]);
                    mma_bf16(d[mi][nj], ah[mi], bl[nj]);
                    mma_bf16(d[mi][nj], al[mi], bh[nj]);
                }
        }
        __syncthreads();
    }

    const int g = lane >> 2;
    const int t2 = (lane & 3) * 2;

    #pragma unroll
    for (int mi = 0; mi < 4; mi++) {
        const int m = m0 + wm * 64 + mi * 16 + g;
        #pragma unroll
        for (int nj = 0; nj < 8; nj++) {
            const int n = n0 + wn * 64 + nj * 8 + t2;
            float c0 = d[mi][nj][0], c1 = d[mi][nj][1];
            float c2 = d[mi][nj][2], c3 = d[mi][nj][3];

            if (MODE == 0) {
                const int which = n >> 10;
                const int nn = n & 1023;
                const float* bp = (which == 0) ? bias0 : (which == 1) ? bias1 : bias2;
                const float sc = (which == 0) ? 0.125f : 1.0f;
                const float bx = bp[nn], by = bp[nn + 1];
                __nv_bfloat16* hA = (which == 0) ? o0h : (which == 1) ? o1h : o2h;
                __nv_bfloat16* lA = (which == 0) ? o0l : (which == 1) ? o1l : o2l;
                const int h = nn >> 6, dh = nn & 63;
                const int b = m >> 11, s_ = m & 2047;
                const size_t i0 = (((size_t)b * HEADS + h) * SEQ + s_) * DHEAD + dh;
                const size_t i1 = (((size_t)b * HEADS + h) * SEQ + s_ + 8) * DHEAD + dh;
                store_hilo(hA, lA, i0, (c0 + bx) * sc, (c1 + by) * sc);
                store_hilo(hA, lA, i1, (c2 + bx) * sc, (c3 + by) * sc);
            } else {
                const float bx = bias0[n], by = bias0[n + 1];
                const size_t i0 = (size_t)m * N + n;
                const size_t i1 = (size_t)(m + 8) * N + n;
                float v00 = c0 + bx, v01 = c1 + by;
                float v10 = c2 + bx, v11 = c3 + by;
                if (MODE == 1 || MODE == 3) {
                    const float2 r0 = *(const float2*)(res + i0);
                    const float2 r1 = *(const float2*)(res + i1);
                    v00 += r0.x; v01 += r0.y; v10 += r1.x; v11 += r1.y;
                }
                if (MODE == 2) {
                    v00 = fmaxf(v00, 0.f); v01 = fmaxf(v01, 0.f);
                    v10 = fmaxf(v10, 0.f); v11 = fmaxf(v11, 0.f);
                }
                if (MODE == 1 || MODE == 3) {
                    *(float2*)(ofp + i0) = make_float2(v00, v01);
                    *(float2*)(ofp + i1) = make_float2(v10, v11);
                }
                if (MODE == 1 || MODE == 2) {
                    store_hilo(o0h, o0l, i0, v00, v01);
                    store_hilo(o0h, o0l, i1, v10, v11);
                }
            }
        }
    }
}

// ===========================================================================
// Tensor-core causal flash attention (split-bf16, FA2 register softmax).
// Block: 128 q-rows of one (b,h), 8 warps x 16 rows. K-tiles of 64.
// ===========================================================================
#define ATT_ROWB 144
#define ATT_QTILE (128*ATT_ROWB)
#define ATT_KV_TILE (64*ATT_ROWB)
#define ATT_STAGE (4*ATT_KV_TILE)
#define ATT_SMEM (2*ATT_QTILE + 2*ATT_STAGE)   // 110592

__global__ void __launch_bounds__(256, 1) flash_attn_tc(
    const __nv_bfloat16* __restrict__ Qh, const __nv_bfloat16* __restrict__ Ql,
    const __nv_bfloat16* __restrict__ Kh, const __nv_bfloat16* __restrict__ Kl,
    const __nv_bfloat16* __restrict__ Vh, const __nv_bfloat16* __restrict__ Vl,
    __nv_bfloat16* __restrict__ Ohi, __nv_bfloat16* __restrict__ Olo)
{
    extern __shared__ char smem[];
    const uint32_t sb = smem_u32(smem);
    const int tid = threadIdx.x;
    const int wid = tid >> 5;
    const int lane = tid & 31;
    const int bh = blockIdx.y;
    const int b  = bh >> 4;
    const int h  = bh & 15;
    const int q0 = blockIdx.x * 128;
    const size_t base = (size_t)bh * SEQ * DHEAD;

    const uint32_t sQ  = sb;
    const uint32_t sKV = sb + 2 * ATT_QTILE;

    // ---- load Q (hi+lo) ----
    #pragma unroll
    for (int i = 0; i < 8; i++) {
        const int t = i >> 2;                          // 0=hi 1=lo
        const int r = (tid >> 3) + 32 * (i & 3);       // 0..127
        const int c = tid & 7;
        const uint32_t dst = sQ + t * ATT_QTILE + r * ATT_ROWB + c * 16;
        const __nv_bfloat16* src = (t == 0 ? Qh : Ql) + base + (size_t)(q0 + r) * DHEAD + c * 8;
        CP_ASYNC16(dst, src);
    }
    CP_COMMIT();

    auto load_kv = [&](int t, int s) {
        const uint32_t stage = sKV + s * ATT_STAGE;
        const int j0 = t * 64;
        #pragma unroll
        for (int i = 0; i < 8; i++) {
            const int tile = i >> 1;                   // 0=Kh 1=Kl 2=Vh 3=Vl
            const int r = (tid >> 3) + 32 * (i & 1);   // 0..63
            const int c = tid & 7;
            const uint32_t dst = stage + tile * ATT_KV_TILE + r * ATT_ROWB + c * 16;
            const __nv_bfloat16* src =
                (tile == 0 ? Kh : tile == 1 ? Kl : tile == 2 ? Vh : Vl)
                + base + (size_t)(j0 + r) * DHEAD + c * 8;
            CP_ASYNC16(dst, src);
        }
    };

    load_kv(0, 0); CP_COMMIT();
    CP_WAIT0();
    __syncthreads();

    // ---- Q fragments into registers ----
    uint32_t qfh[4][4], qfl[4][4];
    #pragma unroll
    for (int kd = 0; kd < 4; kd++) {
        const uint32_t addr = sQ + (wid * 16 + (lane & 15)) * ATT_ROWB
                            + kd * 32 + (lane >> 4) * 16;
        LDSM4(qfh[kd][0], qfh[kd][1], qfh[kd][2], qfh[kd][3], addr);
        LDSM4(qfl[kd][0], qfl[kd][1], qfl[kd][2], qfl[kd][3], addr + ATT_QTILE);
    }

    float m0 = -INFINITY, m1 = -INFINITY, l0 = 0.f, l1 = 0.f;
    float o[8][4];
    #pragma unroll
    for (int nb = 0; nb < 8; nb++)
        #pragma unroll
        for (int e = 0; e < 4; e++) o[nb][e] = 0.f;

    const int numT = 2 * blockIdx.x + 2;
    const int r0 = q0 + wid * 16 + (lane >> 2);
    const int r1 = r0 + 8;

    for (int t = 0; t < numT; t++) {
        const int j0 = t * 64;
        if (t + 1 < numT) load_kv(t + 1, (t + 1) & 1);
        CP_COMMIT();
        CP_WAIT1();
        __syncthreads();

        if (j0 <= q0 + wid * 16 + 15) {
            const uint32_t sK = sKV + (t & 1) * ATT_STAGE;
            const uint32_t sV = sK + 2 * ATT_KV_TILE;

            // ---- S = Q K^T (split 3-product) ----
            float s[8][4];
            #pragma unroll
            for (int nj = 0; nj < 8; nj++)
                #pragma unroll
                for (int e = 0; e < 4; e++) s[nj][e] = 0.f;

            #pragma unroll
            for (int kd = 0; kd < 4; kd++) {
                #pragma unroll
                for (int sjp = 0; sjp < 4; sjp++) {
                    const uint32_t addr = sK + (sjp * 16 + (lane & 15)) * ATT_ROWB
                                        + kd * 32 + (lane >> 4) * 16;
                    uint32_t f0, f1, f2, f3, g0, g1, g2, g3;
                    LDSM4(f0, f1, f2, f3, addr);
                    LDSM4(g0, g1, g2, g3, addr + ATT_KV_TILE);
                    uint32_t bh0[2] = {f0, f2}, bh1[2] = {f1, f3};
                    uint32_t bl0[2] = {g0, g2}, bl1[2] = {g1, g3};
                    mma_bf16(s[2*sjp],   qfh[kd], bh0);
                    mma_bf16(s[2*sjp],   qfh[kd], bl0);
                    mma_bf16(s[2*sjp],   qfl[kd], bh0);
                    mma_bf16(s[2*sjp+1], qfh[kd], bh1);
                    mma_bf16(s[2*sjp+1], qfh[kd], bl1);
                    mma_bf16(s[2*sjp+1], qfl[kd], bh1);
                }
            }

            // ---- causal mask (only last two tiles can touch the diagonal) ----
            if (t >= 2 * blockIdx.x) {
                #pragma unroll
                for (int nj = 0; nj < 8; nj++) {
                    const int c0col = j0 + nj * 8 + (lane & 3) * 2;
                    if (c0col > r0)     s[nj][0] = -INFINITY;
                    if (c0col + 1 > r0) s[nj][1] = -INFINITY;
                    if (c0col > r1)     s[nj][2] = -INFINITY;
                    if (c0col + 1 > r1) s[nj][3] = -INFINITY;
                }
            }

            // ---- online softmax ----
            float t0 = -INFINITY, t1 = -INFINITY;
            #pragma unroll
            for (int nj = 0; nj < 8; nj++) {
                t0 = fmaxf(t0, fmaxf(s[nj][0], s[nj][1]));
                t1 = fmaxf(t1, fmaxf(s[nj][2], s[nj][3]));
            }
            t0 = fmaxf(t0, __shfl_xor_sync(0xffffffffu, t0, 1));
            t0 = fmaxf(t0, __shfl_xor_sync(0xffffffffu, t0, 2));
            t1 = fmaxf(t1, __shfl_xor_sync(0xffffffffu, t1, 1));
            t1 = fmaxf(t1, __shfl_xor_sync(0xffffffffu, t1, 2));
            const float mn0 = fmaxf(m0, t0);
            const float mn1 = fmaxf(m1, t1);
            const float a0 = __expf(m0 - mn0);
            const float a1 = __expf(m1 - mn1);

            float sum0 = 0.f, sum1 = 0.f;
            uint32_t pah[4][4], pal[4][4];
            #pragma unroll
            for (int kk = 0; kk < 4; kk++) {
                float p00 = __expf(s[2*kk][0]   - mn0), p01 = __expf(s[2*kk][1]   - mn0);
                float p02 = __expf(s[2*kk][2]   - mn1), p03 = __expf(s[2*kk][3]   - mn1);
                float p10 = __expf(s[2*kk+1][0] - mn0), p11 = __expf(s[2*kk+1][1] - mn0);
                float p12 = __expf(s[2*kk+1][2] - mn1), p13 = __expf(s[2*kk+1][3] - mn1);
                sum0 += p00 + p01 + p10 + p11;
                sum1 += p02 + p03 + p12 + p13;
                pah[kk][0] = packh_u32(p00, p01); pal[kk][0] = packl_u32(p00, p01, pah[kk][0]);
                pah[kk][1] = packh_u32(p02, p03); pal[kk][1] = packl_u32(p02, p03, pah[kk][1]);
                pah[kk][2] = packh_u32(p10, p11); pal[kk][2] = packl_u32(p10, p11, pah[kk][2]);
                pah[kk][3] = packh_u32(p12, p13); pal[kk][3] = packl_u32(p12, p13, pah[kk][3]);
            }
            l0 = l0 * a0 + sum0;
            l1 = l1 * a1 + sum1;
            #pragma unroll
            for (int nb = 0; nb < 8; nb++) {
                o[nb][0] *= a0; o[nb][1] *= a0;
                o[nb][2] *= a1; o[nb][3] *= a1;
            }

            // ---- O += P V (split 3-product), V via ldmatrix.trans ----
            #pragma unroll
            for (int kk = 0; kk < 4; kk++) {
                #pragma unroll
                for (int nbp = 0; nbp < 4; nbp++) {
                    const uint32_t addr = sV + (kk * 16 + (lane & 15)) * ATT_ROWB
                                        + nbp * 32 + (lane >> 4) * 16;
                    uint32_t f0, f1, f2, f3, g0, g1, g2, g3;
                    LDSM4T(f0, f1, f2, f3, addr);
                    LDSM4T(g0, g1, g2, g3, addr + ATT_KV_TILE);
                    uint32_t vh0[2] = {f0, f1}, vh1[2] = {f2, f3};
                    uint32_t vl0[2] = {g0, g1}, vl1[2] = {g2, g3};
                    mma_bf16(o[2*nbp],   pah[kk], vh0);
                    mma_bf16(o[2*nbp],   pah[kk], vl0);
                    mma_bf16(o[2*nbp],   pal[kk], vh0);
                    mma_bf16(o[2*nbp+1], pah[kk], vh1);
                    mma_bf16(o[2*nbp+1], pah[kk], vl1);
                    mma_bf16(o[2*nbp+1], pal[kk], vh1);
                }
            }
            m0 = mn0; m1 = mn1;
        }
        __syncthreads();
    }

    // ---- epilogue ----
    l0 += __shfl_xor_sync(0xffffffffu, l0, 1);
    l0 += __shfl_xor_sync(0xffffffffu, l0, 2);
    l1 += __shfl_xor_sync(0xffffffffu, l1, 1);
    l1 += __shfl_xor_sync(0xffffffffu, l1, 2);
    const float inv0 = 1.f / l0;
    const float inv1 = 1.f / l1;
    const size_t ro0 = ((size_t)b * SEQ + r0) * DMODEL + h * DHEAD;
    const size_t ro1 = ((size_t)b * SEQ + r1) * DMODEL + h * DHEAD;
    #pragma unroll
    for (int nb = 0; nb < 8; nb++) {
        const int dh = nb * 8 + (lane & 3) * 2;
        store_hilo(Ohi, Olo, ro0 + dh, o[nb][0] * inv0, o[nb][1] * inv0);
        store_hilo(Ohi, Olo, ro1 + dh, o[nb][2] * inv1, o[nb][3] * inv1);
    }
}

// ===========================================================================
// Launch
// ===========================================================================
extern "C" void kernel_launch(void* const* d_in, const int* in_sizes, int n_in,
                              void* d_out, int out_size)
{
    const float* x  = (const float*)d_in[0];
    const float* Wq = (const float*)d_in[1];
    const float* bq = (const float*)d_in[2];
    const float* Wk = (const float*)d_in[3];
    const float* bk = (const float*)d_in[4];
    const float* Wv = (const float*)d_in[5];
    const float* bv = (const float*)d_in[6];
    const float* Wo = (const float*)d_in[7];
    const float* bo = (const float*)d_in[8];
    const float* W1 = (const float*)d_in[9];
    const float* b1 = (const float*)d_in[10];
    const float* W2 = (const float*)d_in[11];
    const float* b2 = (const float*)d_in[12];
    float* out = (float*)d_out;

    __nv_bfloat16 *xh, *xl, *wqkvh, *wqkvl, *woh, *wol, *w1h, *w1l, *w2h, *w2l;
    __nv_bfloat16 *atth, *attl, *x1h, *x1l, *hh, *hl;
    __nv_bfloat16 *qhp, *qlp, *khp, *klp, *vhp, *vlp;
    float *px1;
    cudaGetSymbolAddress((void**)&xh, g_x_hi);       cudaGetSymbolAddress((void**)&xl, g_x_lo);
    cudaGetSymbolAddress((void**)&wqkvh, g_wqkv_hi); cudaGetSymbolAddress((void**)&wqkvl, g_wqkv_lo);
    cudaGetSymbolAddress((void**)&woh, g_wo_hi);     cudaGetSymbolAddress((void**)&wol, g_wo_lo);
    cudaGetSymbolAddress((void**)&w1h, g_w1_hi);     cudaGetSymbolAddress((void**)&w1l, g_w1_lo);
    cudaGetSymbolAddress((void**)&w2h, g_w2_hi);     cudaGetSymbolAddress((void**)&w2l, g_w2_lo);
    cudaGetSymbolAddress((void**)&atth, g_att_hi);   cudaGetSymbolAddress((void**)&attl, g_att_lo);
    cudaGetSymbolAddress((void**)&x1h, g_x1_hi);     cudaGetSymbolAddress((void**)&x1l, g_x1_lo);
    cudaGetSymbolAddress((void**)&hh, g_h_hi);       cudaGetSymbolAddress((void**)&hl, g_h_lo);
    cudaGetSymbolAddress((void**)&qhp, g_q_hi);      cudaGetSymbolAddress((void**)&qlp, g_q_lo);
    cudaGetSymbolAddress((void**)&khp, g_k_hi);      cudaGetSymbolAddress((void**)&klp, g_k_lo);
    cudaGetSymbolAddress((void**)&vhp, g_v_hi);      cudaGetSymbolAddress((void**)&vlp, g_v_lo);
    cudaGetSymbolAddress((void**)&px1, g_x1);

    cudaFuncSetAttribute(tc_gemm<0>, cudaFuncAttributeMaxDynamicSharedMemorySize, GEMM_SMEM);
    cudaFuncSetAttribute(tc_gemm<1>, cudaFuncAttributeMaxDynamicSharedMemorySize, GEMM_SMEM);
    cudaFuncSetAttribute(tc_gemm<2>, cudaFuncAttributeMaxDynamicSharedMemorySize, GEMM_SMEM);
    cudaFuncSetAttribute(tc_gemm<3>, cudaFuncAttributeMaxDynamicSharedMemorySize, GEMM_SMEM);
    cudaFuncSetAttribute(flash_attn_tc, cudaFuncAttributeMaxDynamicSharedMemorySize, ATT_SMEM);

    const int T = 256;
    split_f32<<<(ROWS*DMODEL/4 + T-1)/T, T>>>(x,  xh, xl, ROWS*DMODEL/4);
    split_f32<<<(DMODEL*DMODEL/4 + T-1)/T, T>>>(Wq, wqkvh,                   wqkvl,                   DMODEL*DMODEL/4);
    split_f32<<<(DMODEL*DMODEL/4 + T-1)/T, T>>>(Wk, wqkvh + DMODEL*DMODEL,   wqkvl + DMODEL*DMODEL,   DMODEL*DMODEL/4);
    split_f32<<<(DMODEL*DMODEL/4 + T-1)/T, T>>>(Wv, wqkvh + 2*DMODEL*DMODEL, wqkvl + 2*DMODEL*DMODEL, DMODEL*DMODEL/4);
    split_f32<<<(DMODEL*DMODEL/4 + T-1)/T, T>>>(Wo, woh, wol, DMODEL*DMODEL/4);
    split_f32<<<(FFDIM*DMODEL/4 + T-1)/T, T>>>(W1, w1h, w1l, FFDIM*DMODEL/4);
    split_f32<<<(DMODEL*FFDIM/4 + T-1)/T, T>>>(W2, w2h, w2l, DMODEL*FFDIM/4);

    const dim3 blk(256);

    // QKV combined -> q/k/v bf16 hi/lo [B,H,S,Dh] (q pre-scaled by 1/8)
    tc_gemm<0><<<dim3(3*DMODEL/256, ROWS/128), blk, GEMM_SMEM>>>(
        xh, xl, wqkvh, wqkvl, bq, bk, bv, nullptr,
        nullptr, qhp, qlp, khp, klp, vhp, vlp, ROWS, 3*DMODEL, DMODEL);

    // tensor-core causal attention -> att hi/lo
    flash_attn_tc<<<dim3(SEQ/128, BATCH*HEADS), blk, ATT_SMEM>>>(
        qhp, qlp, khp, klp, vhp, vlp, atth, attl);

    // x1 = att*Wo^T + bo + x  (fp32 + hi/lo)
    tc_gemm<1><<<dim3(DMODEL/256, ROWS/128), blk, GEMM_SMEM>>>(
        atth, attl, woh, wol, bo, nullptr, nullptr, x,
        px1, x1h, x1l, nullptr, nullptr, nullptr, nullptr, ROWS, DMODEL, DMODEL);

    // h = relu(x1*W1^T + b1)  (hi/lo)
    tc_gemm<2><<<dim3(FFDIM/256, ROWS/128), blk, GEMM_SMEM>>>(
        x1h, x1l, w1h, w1l, b1, nullptr, nullptr, nullptr,
        nullptr, hh, hl, nullptr, nullptr, nullptr, nullptr, ROWS, FFDIM, DMODEL);

    // out = h*W2^T + b2 + x1  (fp32)
    tc_gemm<3><<<dim3(DMODEL/256, ROWS/128), blk, GEMM_SMEM>>>(
        hh, hl, w2h, w2l, b2, nullptr, nullptr, px1,
        out, nullptr, nullptr, nullptr, nullptr, nullptr, nullptr, ROWS, DMODEL, FFDIM);
}

// round 6
// speedup vs baseline: 3.6283x; 1.4743x over previous
#include <cuda_runtime.h>
#include <cuda_fp16.h>
#include <cstdint>

// Problem constants
#define BATCH 2
#define SEQ   2048
#define DMODEL 1024
#define HEADS 16
#define DHEAD 64
#define FFDIM 4096
#define ROWS  (BATCH*SEQ)   // 4096

// ===========================================================================
// Scratch (allocation-free: __device__ globals)
// ===========================================================================
__device__ __half g_x_hi[ROWS*DMODEL],  g_x_lo[ROWS*DMODEL];
__device__ __half g_wqkv[3*DMODEL*DMODEL];
__device__ __half g_wo[DMODEL*DMODEL];
__device__ __half g_w1[FFDIM*DMODEL];
__device__ __half g_w2[DMODEL*FFDIM];
__device__ __half g_q_hi[BATCH*HEADS*SEQ*DHEAD], g_q_lo[BATCH*HEADS*SEQ*DHEAD];
__device__ __half g_k[BATCH*HEADS*SEQ*DHEAD];
__device__ __half g_v[BATCH*HEADS*SEQ*DHEAD];
__device__ __half g_att_hi[ROWS*DMODEL], g_att_lo[ROWS*DMODEL];
__device__ float  g_x1[ROWS*DMODEL];
__device__ __half g_x1_hi[ROWS*DMODEL], g_x1_lo[ROWS*DMODEL];
__device__ __half g_h_hi[ROWS*FFDIM],   g_h_lo[ROWS*FFDIM];

// ===========================================================================
// Helpers
// ===========================================================================
__device__ __forceinline__ uint32_t smem_u32(const void* p) {
    uint32_t a;
    asm("{ .reg .u64 t; cvta.to.shared.u64 t, %1; cvt.u32.u64 %0, t; }" : "=r"(a) : "l"(p));
    return a;
}
#define CP_ASYNC16(dst_u32, src_ptr) \
    asm volatile("cp.async.cg.shared.global [%0], [%1], 16;" :: "r"(dst_u32), "l"(src_ptr) : "memory")
#define CP_COMMIT() asm volatile("cp.async.commit_group;" ::: "memory")
#define CP_WAIT0()  asm volatile("cp.async.wait_group 0;" ::: "memory")
#define CP_WAIT1()  asm volatile("cp.async.wait_group 1;" ::: "memory")
#define CP_WAIT3()  asm volatile("cp.async.wait_group 3;" ::: "memory")
#define LDSM4(r0,r1,r2,r3,addr) \
    asm volatile("ldmatrix.sync.aligned.m8n8.x4.shared.b16 {%0,%1,%2,%3}, [%4];" \
        : "=r"(r0), "=r"(r1), "=r"(r2), "=r"(r3) : "r"(addr))
#define LDSM4T(r0,r1,r2,r3,addr) \
    asm volatile("ldmatrix.sync.aligned.m8n8.x4.trans.shared.b16 {%0,%1,%2,%3}, [%4];" \
        : "=r"(r0), "=r"(r1), "=r"(r2), "=r"(r3) : "r"(addr))
__device__ __forceinline__ void mma_fp16(float* d, const uint32_t* a, const uint32_t* b) {
    asm volatile("mma.sync.aligned.m16n8k16.row.col.f32.f16.f16.f32 "
        "{%0,%1,%2,%3}, {%4,%5,%6,%7}, {%8,%9}, {%0,%1,%2,%3};"
        : "+f"(d[0]), "+f"(d[1]), "+f"(d[2]), "+f"(d[3])
        : "r"(a[0]), "r"(a[1]), "r"(a[2]), "r"(a[3]), "r"(b[0]), "r"(b[1]));
}
__device__ __forceinline__ void store_hilo(__half* hi, __half* lo, size_t idx, float a, float b) {
    __half ha = __float2half_rn(a), hb = __float2half_rn(b);
    __half2 hp; hp.x = ha; hp.y = hb;
    __half2 lp;
    lp.x = __float2half_rn(a - __half2float(ha));
    lp.y = __float2half_rn(b - __half2float(hb));
    *(__half2*)(hi + idx) = hp;
    *(__half2*)(lo + idx) = lp;
}
__device__ __forceinline__ uint32_t packh_u32(float a, float b) {
    __half2 p = __floats2half2_rn(a, b);
    return *reinterpret_cast<uint32_t*>(&p);
}
__device__ __forceinline__ uint32_t packl_u32(float a, float b, uint32_t hp_u32) {
    __half2 hp = *reinterpret_cast<__half2*>(&hp_u32);
    return packh_u32(a - __half2float(hp.x), b - __half2float(hp.y));
}

// ===========================================================================
// Converts: x -> fp16 hi/lo split; all weights -> fp16 (single)
// ===========================================================================
__global__ void split2_f32(const float* __restrict__ in, __half* __restrict__ hi,
                           __half* __restrict__ lo, int n4) {
    int i = blockIdx.x * blockDim.x + threadIdx.x;
    if (i >= n4) return;
    float4 v = ((const float4*)in)[i];
    store_hilo(hi, lo, (size_t)i * 4,     v.x, v.y);
    store_hilo(hi, lo, (size_t)i * 4 + 2, v.z, v.w);
}

__global__ void round_weights(const float* __restrict__ Wq, const float* __restrict__ Wk,
                              const float* __restrict__ Wv, const float* __restrict__ Wo,
                              const float* __restrict__ W1, const float* __restrict__ W2,
                              __half* __restrict__ wqkv, __half* __restrict__ wo,
                              __half* __restrict__ w1, __half* __restrict__ w2) {
    const int S1 = DMODEL * DMODEL / 4;  // 262144 float4s per 1Mx weight
    int i = blockIdx.x * blockDim.x + threadIdx.x;
    const float* src; __half* dst; int off;
    if      (i <  S1)     { src = Wq; dst = wqkv;                     off = i; }
    else if (i < 2*S1)    { src = Wk; dst = wqkv + DMODEL*DMODEL;     off = i - S1; }
    else if (i < 3*S1)    { src = Wv; dst = wqkv + 2*DMODEL*DMODEL;   off = i - 2*S1; }
    else if (i < 4*S1)    { src = Wo; dst = wo;                       off = i - 3*S1; }
    else if (i < 8*S1)    { src = W1; dst = w1;                       off = i - 4*S1; }
    else if (i < 12*S1)   { src = W2; dst = w2;                       off = i - 8*S1; }
    else return;
    float4 v = ((const float4*)src)[off];
    *(__half2*)(dst + (size_t)off * 4)     = __floats2half2_rn(v.x, v.y);
    *(__half2*)(dst + (size_t)off * 4 + 2) = __floats2half2_rn(v.z, v.w);
}

// ===========================================================================
// Split-fp16 GEMM (2-product): C = (Ahi+Alo)[M,K] * W[N,K]^T + bias, epilogue:
//   MODE 0: QKV (N=3072) -> q hi/lo (scaled 1/8), k fp16, v fp16 [B,H,S,Dh]
//   MODE 1: Wo: +res(x) -> x1 fp32 AND x1 hi/lo
//   MODE 2: FFN1: relu  -> h hi/lo
//   MODE 3: FFN2: +res(x1) -> out fp32
// Block tile 128x256, BK=32, 8 warps (2x4), warp tile 64x64, 4-stage cp.async.
// ===========================================================================
#define BK 32
#define ROWB 80
#define A_TILE (128 * ROWB)                 // 10240
#define W_TILE (256 * ROWB)                 // 20480
#define STAGE_B (2 * A_TILE + W_TILE)       // 40960
#define NSTAGE 4
#define GEMM_SMEM (NSTAGE * STAGE_B)        // 163840

template<int MODE>
__global__ void __launch_bounds__(256, 1) tc_gemm(
    const __half* __restrict__ Ahi, const __half* __restrict__ Alo,
    const __half* __restrict__ W,
    const float* __restrict__ bias0, const float* __restrict__ bias1, const float* __restrict__ bias2,
    const float* __restrict__ res,
    float* __restrict__ ofp,
    __half* __restrict__ o0h, __half* __restrict__ o0l,
    __half* __restrict__ o1, __half* __restrict__ o2,
    int M, int N, int K)
{
    extern __shared__ char smem[];
    const uint32_t sb = smem_u32(smem);
    const int tid = threadIdx.x;
    const int wid = tid >> 5;
    const int lane = tid & 31;
    const int wm = wid >> 2;
    const int wn = wid & 3;
    const int m0 = blockIdx.y * 128;
    const int n0 = blockIdx.x * 256;
    const int nc = K / BK;

    auto load_chunk = [&](int c, int s) {
        const uint32_t stage = sb + s * STAGE_B;
        const int kbase = c * BK;
        #pragma unroll
        for (int i = 0; i < 8; i++) {
            const int u = tid + 256 * i;                 // 0..2047
            if (u < 1024) {                              // A hi/lo tiles
                const int t = u >> 9;
                const int r = (u >> 2) & 127;
                const int kc = u & 3;
                const uint32_t dst = stage + t * A_TILE + r * ROWB + kc * 16;
                const __half* src = (t == 0 ? Ahi : Alo)
                    + (size_t)(m0 + r) * K + kbase + kc * 8;
                CP_ASYNC16(dst, src);
            } else {                                     // W tile
                const int v = u - 1024;
                const int r = (v >> 2) & 255;
                const int kc = v & 3;
                const uint32_t dst = stage + 2 * A_TILE + r * ROWB + kc * 16;
                const __half* src = W + (size_t)(n0 + r) * K + kbase + kc * 8;
                CP_ASYNC16(dst, src);
            }
        }
    };

    float d[4][8][4];
    #pragma unroll
    for (int i = 0; i < 4; i++)
        #pragma unroll
        for (int j = 0; j < 8; j++)
            #pragma unroll
            for (int e = 0; e < 4; e++) d[i][j][e] = 0.f;

    load_chunk(0, 0); CP_COMMIT();
    load_chunk(1, 1); CP_COMMIT();
    load_chunk(2, 2); CP_COMMIT();

    const int lr = lane & 15;
    const int lh = lane >> 4;

    for (int c = 0; c < nc; c++) {
        if (c + 3 < nc) load_chunk(c + 3, (c + 3) & 3);
        CP_COMMIT();
        CP_WAIT3();
        __syncthreads();

        const uint32_t stage = sb + (c & 3) * STAGE_B;
        const uint32_t sA = stage;
        const uint32_t sW = stage + 2 * A_TILE;

        #pragma unroll
        for (int kk = 0; kk < BK; kk += 16) {
            const uint32_t colb = (kk + lh * 8) * 2;
            uint32_t ah[4][4], al[4][4];
            #pragma unroll
            for (int mi = 0; mi < 4; mi++) {
                const uint32_t rowo = (wm * 64 + mi * 16 + lr) * ROWB + colb;
                LDSM4(ah[mi][0], ah[mi][1], ah[mi][2], ah[mi][3], sA + rowo);
                LDSM4(al[mi][0], al[mi][1], al[mi][2], al[mi][3], sA + A_TILE + rowo);
            }
            uint32_t w[8][2];
            #pragma unroll
            for (int p = 0; p < 4; p++) {
                const uint32_t rowo = (wn * 64 + p * 16 + lr) * ROWB + colb;
                uint32_t r0, r1, r2, r3;
                LDSM4(r0, r1, r2, r3, sW + rowo);
                w[2*p][0] = r0; w[2*p][1] = r2;
                w[2*p+1][0] = r1; w[2*p+1][1] = r3;
            }
            #pragma unroll
            for (int mi = 0; mi < 4; mi++)
                #pragma unroll
                for (int nj = 0; nj < 8; nj++) {
                    mma_fp16(d[mi][nj], ah[mi], w[nj]);
                    mma_fp16(d[mi][nj], al[mi], w[nj]);
                }
        }
        __syncthreads();
    }

    const int g = lane >> 2;
    const int t2 = (lane & 3) * 2;

    #pragma unroll
    for (int mi = 0; mi < 4; mi++) {
        const int m = m0 + wm * 64 + mi * 16 + g;
        #pragma unroll
        for (int nj = 0; nj < 8; nj++) {
            const int n = n0 + wn * 64 + nj * 8 + t2;
            float c0 = d[mi][nj][0], c1 = d[mi][nj][1];
            float c2 = d[mi][nj][2], c3 = d[mi][nj][3];

            if (MODE == 0) {
                const int which = n >> 10;               // uniform per CTA
                const int nn = n & 1023;
                const float* bp = (which == 0) ? bias0 : (which == 1) ? bias1 : bias2;
                const float bx = bp[nn], by = bp[nn + 1];
                const int h = nn >> 6, dh = nn & 63;
                const int b = m >> 11, s_ = m & 2047;
                const size_t i0 = (((size_t)b * HEADS + h) * SEQ + s_) * DHEAD + dh;
                const size_t i1 = (((size_t)b * HEADS + h) * SEQ + s_ + 8) * DHEAD + dh;
                if (which == 0) {
                    store_hilo(o0h, o0l, i0, (c0 + bx) * 0.125f, (c1 + by) * 0.125f);
                    store_hilo(o0h, o0l, i1, (c2 + bx) * 0.125f, (c3 + by) * 0.125f);
                } else {
                    __half* dst = (which == 1) ? o1 : o2;
                    *(__half2*)(dst + i0) = __floats2half2_rn(c0 + bx, c1 + by);
                    *(__half2*)(dst + i1) = __floats2half2_rn(c2 + bx, c3 + by);
                }
            } else {
                const float bx = bias0[n], by = bias0[n + 1];
                const size_t i0 = (size_t)m * N + n;
                const size_t i1 = (size_t)(m + 8) * N + n;
                float v00 = c0 + bx, v01 = c1 + by;
                float v10 = c2 + bx, v11 = c3 + by;
                if (MODE == 1 || MODE == 3) {
                    const float2 r0 = *(const float2*)(res + i0);
                    const float2 r1 = *(const float2*)(res + i1);
                    v00 += r0.x; v01 += r0.y; v10 += r1.x; v11 += r1.y;
                }
                if (MODE == 2) {
                    v00 = fmaxf(v00, 0.f); v01 = fmaxf(v01, 0.f);
                    v10 = fmaxf(v10, 0.f); v11 = fmaxf(v11, 0.f);
                }
                if (MODE == 1 || MODE == 3) {
                    *(float2*)(ofp + i0) = make_float2(v00, v01);
                    *(float2*)(ofp + i1) = make_float2(v10, v11);
                }
                if (MODE == 1 || MODE == 2) {
                    store_hilo(o0h, o0l, i0, v00, v01);
                    store_hilo(o0h, o0l, i1, v10, v11);
                }
            }
        }
    }
}

// ===========================================================================
// Tensor-core causal flash attention (fp16 2-product).
// Q split hi/lo (pre-scaled 1/8); K, V single fp16.
// Block: 128 q-rows of one (b,h), 8 warps x 16 rows. K-tiles of 64, 2-stage.
// ===========================================================================
#define ATT_ROWB 144
#define ATT_QTILE (128*ATT_ROWB)              // 18432
#define ATT_KV_TILE (64*ATT_ROWB)             // 9216
#define ATT_STAGE (2*ATT_KV_TILE)             // 18432
#define ATT_SMEM (2*ATT_QTILE + 2*ATT_STAGE)  // 73728

__global__ void __launch_bounds__(256, 1) flash_attn_tc(
    const __half* __restrict__ Qh, const __half* __restrict__ Ql,
    const __half* __restrict__ Kg, const __half* __restrict__ Vg,
    __half* __restrict__ Ohi, __half* __restrict__ Olo)
{
    extern __shared__ char smem[];
    const uint32_t sb = smem_u32(smem);
    const int tid = threadIdx.x;
    const int wid = tid >> 5;
    const int lane = tid & 31;
    const int bh = blockIdx.y;
    const int b  = bh >> 4;
    const int h  = bh & 15;
    const int q0 = blockIdx.x * 128;
    const size_t base = (size_t)bh * SEQ * DHEAD;

    const uint32_t sQ  = sb;
    const uint32_t sKV = sb + 2 * ATT_QTILE;

    // ---- load Q hi/lo ----
    #pragma unroll
    for (int i = 0; i < 8; i++) {
        const int u = tid + 256 * i;                   // 0..2047
        const int t = u >> 10;                         // 0=hi 1=lo
        const int w = u & 1023;
        const int r = w >> 3, c = w & 7;
        const uint32_t dst = sQ + t * ATT_QTILE + r * ATT_ROWB + c * 16;
        const __half* src = (t == 0 ? Qh : Ql) + base + (size_t)(q0 + r) * DHEAD + c * 8;
        CP_ASYNC16(dst, src);
    }
    CP_COMMIT();

    auto load_kv = [&](int t, int s) {
        const uint32_t stage = sKV + s * ATT_STAGE;
        const int j0 = t * 64;
        #pragma unroll
        for (int i = 0; i < 4; i++) {
            const int u = tid + 256 * i;               // 0..1023
            const int tile = u >> 9;                   // 0=K 1=V
            const int w = u & 511;
            const int r = w >> 3, c = w & 7;
            const uint32_t dst = stage + tile * ATT_KV_TILE + r * ATT_ROWB + c * 16;
            const __half* src = (tile == 0 ? Kg : Vg) + base + (size_t)(j0 + r) * DHEAD + c * 8;
            CP_ASYNC16(dst, src);
        }
    };

    load_kv(0, 0); CP_COMMIT();
    CP_WAIT0();
    __syncthreads();

    // ---- Q fragments into registers ----
    uint32_t qfh[4][4], qfl[4][4];
    #pragma unroll
    for (int kd = 0; kd < 4; kd++) {
        const uint32_t addr = sQ + (wid * 16 + (lane & 15)) * ATT_ROWB
                            + kd * 32 + (lane >> 4) * 16;
        LDSM4(qfh[kd][0], qfh[kd][1], qfh[kd][2], qfh[kd][3], addr);
        LDSM4(qfl[kd][0], qfl[kd][1], qfl[kd][2], qfl[kd][3], addr + ATT_QTILE);
    }

    float m0 = -INFINITY, m1 = -INFINITY, l0 = 0.f, l1 = 0.f;
    float o[8][4];
    #pragma unroll
    for (int nb = 0; nb < 8; nb++)
        #pragma unroll
        for (int e = 0; e < 4; e++) o[nb][e] = 0.f;

    const int numT = 2 * blockIdx.x + 2;
    const int r0 = q0 + wid * 16 + (lane >> 2);
    const int r1 = r0 + 8;

    for (int t = 0; t < numT; t++) {
        const int j0 = t * 64;
        if (t + 1 < numT) load_kv(t + 1, (t + 1) & 1);
        CP_COMMIT();
        CP_WAIT1();
        __syncthreads();

        if (j0 <= q0 + wid * 16 + 15) {
            const uint32_t sK = sKV + (t & 1) * ATT_STAGE;
            const uint32_t sV = sK + ATT_KV_TILE;

            // ---- S = Q K^T (2-product) ----
            float s[8][4];
            #pragma unroll
            for (int nj = 0; nj < 8; nj++)
                #pragma unroll
                for (int e = 0; e < 4; e++) s[nj][e] = 0.f;

            #pragma unroll
            for (int kd = 0; kd < 4; kd++) {
                #pragma unroll
                for (int sjp = 0; sjp < 4; sjp++) {
                    const uint32_t addr = sK + (sjp * 16 + (lane & 15)) * ATT_ROWB
                                        + kd * 32 + (lane >> 4) * 16;
                    uint32_t f0, f1, f2, f3;
                    LDSM4(f0, f1, f2, f3, addr);
                    uint32_t b0[2] = {f0, f2}, b1[2] = {f1, f3};
                    mma_fp16(s[2*sjp],   qfh[kd], b0);
                    mma_fp16(s[2*sjp],   qfl[kd], b0);
                    mma_fp16(s[2*sjp+1], qfh[kd], b1);
                    mma_fp16(s[2*sjp+1], qfl[kd], b1);
                }
            }

            // ---- causal mask ----
            if (t >= 2 * blockIdx.x) {
                #pragma unroll
                for (int nj = 0; nj < 8; nj++) {
                    const int c0col = j0 + nj * 8 + (lane & 3) * 2;
                    if (c0col > r0)     s[nj][0] = -INFINITY;
                    if (c0col + 1 > r0) s[nj][1] = -INFINITY;
                    if (c0col > r1)     s[nj][2] = -INFINITY;
                    if (c0col + 1 > r1) s[nj][3] = -INFINITY;
                }
            }

            // ---- online softmax ----
            float t0 = -INFINITY, t1 = -INFINITY;
            #pragma unroll
            for (int nj = 0; nj < 8; nj++) {
                t0 = fmaxf(t0, fmaxf(s[nj][0], s[nj][1]));
                t1 = fmaxf(t1, fmaxf(s[nj][2], s[nj][3]));
            }
            t0 = fmaxf(t0, __shfl_xor_sync(0xffffffffu, t0, 1));
            t0 = fmaxf(t0, __shfl_xor_sync(0xffffffffu, t0, 2));
            t1 = fmaxf(t1, __shfl_xor_sync(0xffffffffu, t1, 1));
            t1 = fmaxf(t1, __shfl_xor_sync(0xffffffffu, t1, 2));
            const float mn0 = fmaxf(m0, t0);
            const float mn1 = fmaxf(m1, t1);
            const float a0 = __expf(m0 - mn0);
            const float a1 = __expf(m1 - mn1);

            float sum0 = 0.f, sum1 = 0.f;
            uint32_t pah[4][4], pal[4][4];
            #pragma unroll
            for (int kk = 0; kk < 4; kk++) {
                float p00 = __expf(s[2*kk][0]   - mn0), p01 = __expf(s[2*kk][1]   - mn0);
                float p02 = __expf(s[2*kk][2]   - mn1), p03 = __expf(s[2*kk][3]   - mn1);
                float p10 = __expf(s[2*kk+1][0] - mn0), p11 = __expf(s[2*kk+1][1] - mn0);
                float p12 = __expf(s[2*kk+1][2] - mn1), p13 = __expf(s[2*kk+1][3] - mn1);
                sum0 += p00 + p01 + p10 + p11;
                sum1 += p02 + p03 + p12 + p13;
                pah[kk][0] = packh_u32(p00, p01); pal[kk][0] = packl_u32(p00, p01, pah[kk][0]);
                pah[kk][1] = packh_u32(p02, p03); pal[kk][1] = packl_u32(p02, p03, pah[kk][1]);
                pah[kk][2] = packh_u32(p10, p11); pal[kk][2] = packl_u32(p10, p11, pah[kk][2]);
                pah[kk][3] = packh_u32(p12, p13); pal[kk][3] = packl_u32(p12, p13, pah[kk][3]);
            }
            l0 = l0 * a0 + sum0;
            l1 = l1 * a1 + sum1;
            #pragma unroll
            for (int nb = 0; nb < 8; nb++) {
                o[nb][0] *= a0; o[nb][1] *= a0;
                o[nb][2] *= a1; o[nb][3] *= a1;
            }

            // ---- O += P V (2-product: P split, V single) ----
            #pragma unroll
            for (int kk = 0; kk < 4; kk++) {
                #pragma unroll
                for (int nbp = 0; nbp < 4; nbp++) {
                    const uint32_t addr = sV + (kk * 16 + (lane & 15)) * ATT_ROWB
                                        + nbp * 32 + (lane >> 4) * 16;
                    uint32_t f0, f1, f2, f3;
                    LDSM4T(f0, f1, f2, f3, addr);
                    uint32_t v0[2] = {f0, f1}, v1[2] = {f2, f3};
                    mma_fp16(o[2*nbp],   pah[kk], v0);
                    mma_fp16(o[2*nbp],   pal[kk], v0);
                    mma_fp16(o[2*nbp+1], pah[kk], v1);
                    mma_fp16(o[2*nbp+1], pal[kk], v1);
                }
            }
            m0 = mn0; m1 = mn1;
        }
        __syncthreads();
    }

    // ---- epilogue ----
    l0 += __shfl_xor_sync(0xffffffffu, l0, 1);
    l0 += __shfl_xor_sync(0xffffffffu, l0, 2);
    l1 += __shfl_xor_sync(0xffffffffu, l1, 1);
    l1 += __shfl_xor_sync(0xffffffffu, l1, 2);
    const float inv0 = 1.f / l0;
    const float inv1 = 1.f / l1;
    const size_t ro0 = ((size_t)b * SEQ + r0) * DMODEL + h * DHEAD;
    const size_t ro1 = ((size_t)b * SEQ + r1) * DMODEL + h * DHEAD;
    #pragma unroll
    for (int nb = 0; nb < 8; nb++) {
        const int dh = nb * 8 + (lane & 3) * 2;
        store_hilo(Ohi, Olo, ro0 + dh, o[nb][0] * inv0, o[nb][1] * inv0);
        store_hilo(Ohi, Olo, ro1 + dh, o[nb][2] * inv1, o[nb][3] * inv1);
    }
}

// ===========================================================================
// Launch
// ===========================================================================
extern "C" void kernel_launch(void* const* d_in, const int* in_sizes, int n_in,
                              void* d_out, int out_size)
{
    const float* x  = (const float*)d_in[0];
    const float* Wq = (const float*)d_in[1];
    const float* bq = (const float*)d_in[2];
    const float* Wk = (const float*)d_in[3];
    const float* bk = (const float*)d_in[4];
    const float* Wv = (const float*)d_in[5];
    const float* bv = (const float*)d_in[6];
    const float* Wo = (const float*)d_in[7];
    const float* bo = (const float*)d_in[8];
    const float* W1 = (const float*)d_in[9];
    const float* b1 = (const float*)d_in[10];
    const float* W2 = (const float*)d_in[11];
    const float* b2 = (const float*)d_in[12];
    float* out = (float*)d_out;

    __half *xh, *xl, *wqkv, *wo, *w1, *w2;
    __half *atth, *attl, *x1h, *x1l, *hh, *hl;
    __half *qhp, *qlp, *kp, *vp;
    float *px1;
    cudaGetSymbolAddress((void**)&xh, g_x_hi);     cudaGetSymbolAddress((void**)&xl, g_x_lo);
    cudaGetSymbolAddress((void**)&wqkv, g_wqkv);   cudaGetSymbolAddress((void**)&wo, g_wo);
    cudaGetSymbolAddress((void**)&w1, g_w1);       cudaGetSymbolAddress((void**)&w2, g_w2);
    cudaGetSymbolAddress((void**)&atth, g_att_hi); cudaGetSymbolAddress((void**)&attl, g_att_lo);
    cudaGetSymbolAddress((void**)&x1h, g_x1_hi);   cudaGetSymbolAddress((void**)&x1l, g_x1_lo);
    cudaGetSymbolAddress((void**)&hh, g_h_hi);     cudaGetSymbolAddress((void**)&hl, g_h_lo);
    cudaGetSymbolAddress((void**)&qhp, g_q_hi);    cudaGetSymbolAddress((void**)&qlp, g_q_lo);
    cudaGetSymbolAddress((void**)&kp, g_k);        cudaGetSymbolAddress((void**)&vp, g_v);
    cudaGetSymbolAddress((void**)&px1, g_x1);

    cudaFuncSetAttribute(tc_gemm<0>, cudaFuncAttributeMaxDynamicSharedMemorySize, GEMM_SMEM);
    cudaFuncSetAttribute(tc_gemm<1>, cudaFuncAttributeMaxDynamicSharedMemorySize, GEMM_SMEM);
    cudaFuncSetAttribute(tc_gemm<2>, cudaFuncAttributeMaxDynamicSharedMemorySize, GEMM_SMEM);
    cudaFuncSetAttribute(tc_gemm<3>, cudaFuncAttributeMaxDynamicSharedMemorySize, GEMM_SMEM);
    cudaFuncSetAttribute(flash_attn_tc, cudaFuncAttributeMaxDynamicSharedMemorySize, ATT_SMEM);

    const int T = 256;

    // (1) x -> fp16 hi/lo
    split2_f32<<<(ROWS*DMODEL/4 + T-1)/T, T>>>(x, xh, xl, ROWS*DMODEL/4);
    // (2) all weights -> fp16 (single kernel)
    round_weights<<<(12*DMODEL*DMODEL/4 + T-1)/T, T>>>(Wq, Wk, Wv, Wo, W1, W2,
                                                       wqkv, wo, w1, w2);

    const dim3 blk(256);

    // (3) QKV combined -> q hi/lo (scaled), k, v  [B,H,S,Dh]
    tc_gemm<0><<<dim3(3*DMODEL/256, ROWS/128), blk, GEMM_SMEM>>>(
        xh, xl, wqkv, bq, bk, bv, nullptr,
        nullptr, qhp, qlp, kp, vp, ROWS, 3*DMODEL, DMODEL);

    // (4) tensor-core causal attention -> att hi/lo
    flash_attn_tc<<<dim3(SEQ/128, BATCH*HEADS), blk, ATT_SMEM>>>(
        qhp, qlp, kp, vp, atth, attl);

    // (5) x1 = att*Wo^T + bo + x  (fp32 + hi/lo)
    tc_gemm<1><<<dim3(DMODEL/256, ROWS/128), blk, GEMM_SMEM>>>(
        atth, attl, wo, bo, nullptr, nullptr, x,
        px1, x1h, x1l, nullptr, nullptr, ROWS, DMODEL, DMODEL);

    // (6) h = relu(x1*W1^T + b1)  (hi/lo)   <- ncu -s 5 -c 1 captures this
    tc_gemm<2><<<dim3(FFDIM/256, ROWS/128), blk, GEMM_SMEM>>>(
        x1h, x1l, w1, b1, nullptr, nullptr, nullptr,
        nullptr, hh, hl, nullptr, nullptr, ROWS, FFDIM, DMODEL);

    // (7) out = h*W2^T + b2 + x1  (fp32)
    tc_gemm<3><<<dim3(DMODEL/256, ROWS/128), blk, GEMM_SMEM>>>(
        hh, hl, w2, b2, nullptr, nullptr, px1,
        out, nullptr, nullptr, nullptr, nullptr, ROWS, DMODEL, FFDIM);
}

// round 7
// speedup vs baseline: 5.4952x; 1.5145x over previous
#include <cuda_runtime.h>
#include <cuda_fp16.h>
#include <cstdint>

// Problem constants
#define BATCH 2
#define SEQ   2048
#define DMODEL 1024
#define HEADS 16
#define DHEAD 64
#define FFDIM 4096
#define ROWS  (BATCH*SEQ)   // 4096

// ===========================================================================
// Scratch (allocation-free: __device__ globals)
// ===========================================================================
__device__ __half g_x[ROWS*DMODEL];
__device__ __half g_wqkv[3*DMODEL*DMODEL];
__device__ __half g_wo[DMODEL*DMODEL];
__device__ __half g_w1[FFDIM*DMODEL];
__device__ __half g_w2[DMODEL*FFDIM];
__device__ __half g_q[BATCH*HEADS*SEQ*DHEAD];
__device__ __half g_k[BATCH*HEADS*SEQ*DHEAD];
__device__ __half g_v[BATCH*HEADS*SEQ*DHEAD];
__device__ __half g_att[ROWS*DMODEL];
__device__ float  g_x1[ROWS*DMODEL];
__device__ __half g_x1h[ROWS*DMODEL];
__device__ __half g_h[ROWS*FFDIM];

// ===========================================================================
// Helpers
// ===========================================================================
__device__ __forceinline__ uint32_t smem_u32(const void* p) {
    uint32_t a;
    asm("{ .reg .u64 t; cvta.to.shared.u64 t, %1; cvt.u32.u64 %0, t; }" : "=r"(a) : "l"(p));
    return a;
}
#define CP_ASYNC16(dst_u32, src_ptr) \
    asm volatile("cp.async.cg.shared.global [%0], [%1], 16;" :: "r"(dst_u32), "l"(src_ptr) : "memory")
#define CP_COMMIT() asm volatile("cp.async.commit_group;" ::: "memory")
#define CP_WAIT0()  asm volatile("cp.async.wait_group 0;" ::: "memory")
#define CP_WAIT1()  asm volatile("cp.async.wait_group 1;" ::: "memory")
#define CP_WAIT4()  asm volatile("cp.async.wait_group 4;" ::: "memory")
#define LDSM4(r0,r1,r2,r3,addr) \
    asm volatile("ldmatrix.sync.aligned.m8n8.x4.shared.b16 {%0,%1,%2,%3}, [%4];" \
        : "=r"(r0), "=r"(r1), "=r"(r2), "=r"(r3) : "r"(addr))
#define LDSM4T(r0,r1,r2,r3,addr) \
    asm volatile("ldmatrix.sync.aligned.m8n8.x4.trans.shared.b16 {%0,%1,%2,%3}, [%4];" \
        : "=r"(r0), "=r"(r1), "=r"(r2), "=r"(r3) : "r"(addr))
__device__ __forceinline__ void mma_fp16(float* d, const uint32_t* a, const uint32_t* b) {
    asm volatile("mma.sync.aligned.m16n8k16.row.col.f32.f16.f16.f32 "
        "{%0,%1,%2,%3}, {%4,%5,%6,%7}, {%8,%9}, {%0,%1,%2,%3};"
        : "+f"(d[0]), "+f"(d[1]), "+f"(d[2]), "+f"(d[3])
        : "r"(a[0]), "r"(a[1]), "r"(a[2]), "r"(a[3]), "r"(b[0]), "r"(b[1]));
}
__device__ __forceinline__ uint32_t packh_u32(float a, float b) {
    __half2 p = __floats2half2_rn(a, b);
    return *reinterpret_cast<uint32_t*>(&p);
}
__device__ __forceinline__ uint32_t packl_u32(float a, float b, uint32_t hp_u32) {
    __half2 hp = *reinterpret_cast<__half2*>(&hp_u32);
    return packh_u32(a - __half2float(hp.x), b - __half2float(hp.y));
}

// ===========================================================================
// One rounding kernel: x + all weights -> fp16
// layout: [x(4S), Wq(S), Wk(S), Wv(S), Wo(S), W1(4S), W2(4S)], S = DMODEL^2/4
// ===========================================================================
__global__ void round_all(const float* __restrict__ x,
                          const float* __restrict__ Wq, const float* __restrict__ Wk,
                          const float* __restrict__ Wv, const float* __restrict__ Wo,
                          const float* __restrict__ W1, const float* __restrict__ W2,
                          __half* __restrict__ xh, __half* __restrict__ wqkv,
                          __half* __restrict__ wo, __half* __restrict__ w1,
                          __half* __restrict__ w2) {
    const int S1 = DMODEL * DMODEL / 4;
    int i = blockIdx.x * blockDim.x + threadIdx.x;
    const float* src; __half* dst; int off;
    if      (i <  4*S1)  { src = x;  dst = xh;                      off = i; }
    else if (i <  5*S1)  { src = Wq; dst = wqkv;                    off = i - 4*S1; }
    else if (i <  6*S1)  { src = Wk; dst = wqkv + DMODEL*DMODEL;    off = i - 5*S1; }
    else if (i <  7*S1)  { src = Wv; dst = wqkv + 2*DMODEL*DMODEL;  off = i - 6*S1; }
    else if (i <  8*S1)  { src = Wo; dst = wo;                      off = i - 7*S1; }
    else if (i < 12*S1)  { src = W1; dst = w1;                      off = i - 8*S1; }
    else if (i < 16*S1)  { src = W2; dst = w2;                      off = i - 12*S1; }
    else return;
    float4 v = ((const float4*)src)[off];
    *(__half2*)(dst + (size_t)off * 4)     = __floats2half2_rn(v.x, v.y);
    *(__half2*)(dst + (size_t)off * 4 + 2) = __floats2half2_rn(v.z, v.w);
}

// ===========================================================================
// fp16 GEMM: C[M,N] = A[M,K] * W[N,K]^T + bias, epilogue by MODE:
//   MODE 0: QKV (N=3072) -> q (scaled 1/8), k, v  fp16 [B,H,S,Dh]
//   MODE 1: Wo: +res(x) -> x1 fp32 AND x1 fp16
//   MODE 2: FFN1: relu  -> h fp16
//   MODE 3: FFN2: +res(x1) -> out fp32
// 512 threads = 16 warps as 2(M) x 8(N); block tile 128x256; warp tile 64x32;
// BK=32; 5-stage cp.async pipeline.
// ===========================================================================
#define BK 32
#define ROWB 80
#define A_TILE (128 * ROWB)                 // 10240
#define W_TILE (256 * ROWB)                 // 20480
#define STAGE_B (A_TILE + W_TILE)           // 30720
#define NSTAGE 5
#define GEMM_SMEM (NSTAGE * STAGE_B)        // 153600

template<int MODE>
__global__ void __launch_bounds__(512, 1) tc_gemm(
    const __half* __restrict__ A, const __half* __restrict__ W,
    const float* __restrict__ bias0, const float* __restrict__ bias1, const float* __restrict__ bias2,
    const float* __restrict__ res,
    float* __restrict__ ofp,
    __half* __restrict__ o0, __half* __restrict__ o1, __half* __restrict__ o2,
    int M, int N, int K)
{
    extern __shared__ char smem[];
    const uint32_t sb = smem_u32(smem);
    const int tid = threadIdx.x;
    const int wid = tid >> 5;
    const int lane = tid & 31;
    const int wm = wid >> 3;            // 0..1
    const int wn = wid & 7;             // 0..7
    const int m0 = blockIdx.y * 128;
    const int n0 = blockIdx.x * 256;
    const int nc = K / BK;

    auto load_chunk = [&](int c, int s) {
        const uint32_t stage = sb + s * STAGE_B;
        const int kbase = c * BK;
        #pragma unroll
        for (int i = 0; i < 3; i++) {
            const int u = tid + 512 * i;                 // 0..1535
            if (u < 512) {                               // A tile 128x32
                const int r = u >> 2;
                const int kc = u & 3;
                const uint32_t dst = stage + r * ROWB + kc * 16;
                CP_ASYNC16(dst, A + (size_t)(m0 + r) * K + kbase + kc * 8);
            } else {                                     // W tile 256x32
                const int v = u - 512;
                const int r = v >> 2;
                const int kc = v & 3;
                const uint32_t dst = stage + A_TILE + r * ROWB + kc * 16;
                CP_ASYNC16(dst, W + (size_t)(n0 + r) * K + kbase + kc * 8);
            }
        }
    };

    float d[4][4][4];
    #pragma unroll
    for (int i = 0; i < 4; i++)
        #pragma unroll
        for (int j = 0; j < 4; j++)
            #pragma unroll
            for (int e = 0; e < 4; e++) d[i][j][e] = 0.f;

    load_chunk(0, 0); CP_COMMIT();
    load_chunk(1, 1); CP_COMMIT();
    load_chunk(2, 2); CP_COMMIT();
    load_chunk(3, 3); CP_COMMIT();

    const int lr = lane & 15;
    const int lh = lane >> 4;

    for (int c = 0; c < nc; c++) {
        if (c + 4 < nc) load_chunk(c + 4, (c + 4) % NSTAGE);
        CP_COMMIT();
        CP_WAIT4();
        __syncthreads();

        const uint32_t stage = sb + (c % NSTAGE) * STAGE_B;
        const uint32_t sA = stage;
        const uint32_t sW = stage + A_TILE;

        #pragma unroll
        for (int kk = 0; kk < BK; kk += 16) {
            const uint32_t colb = (kk + lh * 8) * 2;
            uint32_t ah[4][4];
            #pragma unroll
            for (int mi = 0; mi < 4; mi++) {
                const uint32_t rowo = (wm * 64 + mi * 16 + lr) * ROWB + colb;
                LDSM4(ah[mi][0], ah[mi][1], ah[mi][2], ah[mi][3], sA + rowo);
            }
            uint32_t w[4][2];
            #pragma unroll
            for (int p = 0; p < 2; p++) {
                const uint32_t rowo = (wn * 32 + p * 16 + lr) * ROWB + colb;
                uint32_t r0, r1, r2, r3;
                LDSM4(r0, r1, r2, r3, sW + rowo);
                w[2*p][0] = r0; w[2*p][1] = r2;
                w[2*p+1][0] = r1; w[2*p+1][1] = r3;
            }
            #pragma unroll
            for (int mi = 0; mi < 4; mi++)
                #pragma unroll
                for (int nj = 0; nj < 4; nj++)
                    mma_fp16(d[mi][nj], ah[mi], w[nj]);
        }
        __syncthreads();
    }

    const int g = lane >> 2;
    const int t2 = (lane & 3) * 2;

    #pragma unroll
    for (int mi = 0; mi < 4; mi++) {
        const int m = m0 + wm * 64 + mi * 16 + g;
        #pragma unroll
        for (int nj = 0; nj < 4; nj++) {
            const int n = n0 + wn * 32 + nj * 8 + t2;
            float c0 = d[mi][nj][0], c1 = d[mi][nj][1];
            float c2 = d[mi][nj][2], c3 = d[mi][nj][3];

            if (MODE == 0) {
                const int which = n >> 10;               // uniform per CTA
                const int nn = n & 1023;
                const float* bp = (which == 0) ? bias0 : (which == 1) ? bias1 : bias2;
                const float sc = (which == 0) ? 0.125f : 1.0f;
                const float bx = bp[nn], by = bp[nn + 1];
                __half* dst = (which == 0) ? o0 : (which == 1) ? o1 : o2;
                const int h = nn >> 6, dh = nn & 63;
                const int b = m >> 11, s_ = m & 2047;
                const size_t i0 = (((size_t)b * HEADS + h) * SEQ + s_) * DHEAD + dh;
                const size_t i1 = (((size_t)b * HEADS + h) * SEQ + s_ + 8) * DHEAD + dh;
                *(__half2*)(dst + i0) = __floats2half2_rn((c0 + bx) * sc, (c1 + by) * sc);
                *(__half2*)(dst + i1) = __floats2half2_rn((c2 + bx) * sc, (c3 + by) * sc);
            } else {
                const float bx = bias0[n], by = bias0[n + 1];
                const size_t i0 = (size_t)m * N + n;
                const size_t i1 = (size_t)(m + 8) * N + n;
                float v00 = c0 + bx, v01 = c1 + by;
                float v10 = c2 + bx, v11 = c3 + by;
                if (MODE == 1 || MODE == 3) {
                    const float2 r0 = *(const float2*)(res + i0);
                    const float2 r1 = *(const float2*)(res + i1);
                    v00 += r0.x; v01 += r0.y; v10 += r1.x; v11 += r1.y;
                }
                if (MODE == 2) {
                    v00 = fmaxf(v00, 0.f); v01 = fmaxf(v01, 0.f);
                    v10 = fmaxf(v10, 0.f); v11 = fmaxf(v11, 0.f);
                }
                if (MODE == 1 || MODE == 3) {
                    *(float2*)(ofp + i0) = make_float2(v00, v01);
                    *(float2*)(ofp + i1) = make_float2(v10, v11);
                }
                if (MODE == 1 || MODE == 2) {
                    *(__half2*)(o0 + i0) = __floats2half2_rn(v00, v01);
                    *(__half2*)(o0 + i1) = __floats2half2_rn(v10, v11);
                }
            }
        }
    }
}

// ===========================================================================
// Tensor-core causal flash attention.
// Q single fp16 (pre-scaled 1/8) -> 1-product QK^T; P split hi/lo -> 2-product PV.
// Block: 128 q-rows of one (b,h), 8 warps x 16 rows. K-tiles of 64, 2-stage.
// ===========================================================================
#define ATT_ROWB 144
#define ATT_QTILE (128*ATT_ROWB)              // 18432
#define ATT_KV_TILE (64*ATT_ROWB)             // 9216
#define ATT_STAGE (2*ATT_KV_TILE)             // 18432
#define ATT_SMEM (ATT_QTILE + 2*ATT_STAGE)    // 55296

__global__ void __launch_bounds__(256, 1) flash_attn_tc(
    const __half* __restrict__ Qg,
    const __half* __restrict__ Kg, const __half* __restrict__ Vg,
    __half* __restrict__ Og)
{
    extern __shared__ char smem[];
    const uint32_t sb = smem_u32(smem);
    const int tid = threadIdx.x;
    const int wid = tid >> 5;
    const int lane = tid & 31;
    const int bh = blockIdx.y;
    const int b  = bh >> 4;
    const int h  = bh & 15;
    const int q0 = blockIdx.x * 128;
    const size_t base = (size_t)bh * SEQ * DHEAD;

    const uint32_t sQ  = sb;
    const uint32_t sKV = sb + ATT_QTILE;

    // ---- load Q ----
    #pragma unroll
    for (int i = 0; i < 4; i++) {
        const int u = tid + 256 * i;                   // 0..1023
        const int r = u >> 3, c = u & 7;
        const uint32_t dst = sQ + r * ATT_ROWB + c * 16;
        CP_ASYNC16(dst, Qg + base + (size_t)(q0 + r) * DHEAD + c * 8);
    }
    CP_COMMIT();

    auto load_kv = [&](int t, int s) {
        const uint32_t stage = sKV + s * ATT_STAGE;
        const int j0 = t * 64;
        #pragma unroll
        for (int i = 0; i < 4; i++) {
            const int u = tid + 256 * i;               // 0..1023
            const int tile = u >> 9;                   // 0=K 1=V
            const int w = u & 511;
            const int r = w >> 3, c = w & 7;
            const uint32_t dst = stage + tile * ATT_KV_TILE + r * ATT_ROWB + c * 16;
            const __half* src = (tile == 0 ? Kg : Vg) + base + (size_t)(j0 + r) * DHEAD + c * 8;
            CP_ASYNC16(dst, src);
        }
    };

    load_kv(0, 0); CP_COMMIT();
    CP_WAIT0();
    __syncthreads();

    // ---- Q fragments into registers ----
    uint32_t qf[4][4];
    #pragma unroll
    for (int kd = 0; kd < 4; kd++) {
        const uint32_t addr = sQ + (wid * 16 + (lane & 15)) * ATT_ROWB
                            + kd * 32 + (lane >> 4) * 16;
        LDSM4(qf[kd][0], qf[kd][1], qf[kd][2], qf[kd][3], addr);
    }

    float m0 = -INFINITY, m1 = -INFINITY, l0 = 0.f, l1 = 0.f;
    float o[8][4];
    #pragma unroll
    for (int nb = 0; nb < 8; nb++)
        #pragma unroll
        for (int e = 0; e < 4; e++) o[nb][e] = 0.f;

    const int numT = 2 * blockIdx.x + 2;
    const int r0 = q0 + wid * 16 + (lane >> 2);
    const int r1 = r0 + 8;

    for (int t = 0; t < numT; t++) {
        const int j0 = t * 64;
        if (t + 1 < numT) load_kv(t + 1, (t + 1) & 1);
        CP_COMMIT();
        CP_WAIT1();
        __syncthreads();

        if (j0 <= q0 + wid * 16 + 15) {
            const uint32_t sK = sKV + (t & 1) * ATT_STAGE;
            const uint32_t sV = sK + ATT_KV_TILE;

            // ---- S = Q K^T (single product) ----
            float s[8][4];
            #pragma unroll
            for (int nj = 0; nj < 8; nj++)
                #pragma unroll
                for (int e = 0; e < 4; e++) s[nj][e] = 0.f;

            #pragma unroll
            for (int kd = 0; kd < 4; kd++) {
                #pragma unroll
                for (int sjp = 0; sjp < 4; sjp++) {
                    const uint32_t addr = sK + (sjp * 16 + (lane & 15)) * ATT_ROWB
                                        + kd * 32 + (lane >> 4) * 16;
                    uint32_t f0, f1, f2, f3;
                    LDSM4(f0, f1, f2, f3, addr);
                    uint32_t b0[2] = {f0, f2}, b1[2] = {f1, f3};
                    mma_fp16(s[2*sjp],   qf[kd], b0);
                    mma_fp16(s[2*sjp+1], qf[kd], b1);
                }
            }

            // ---- causal mask ----
            if (t >= 2 * blockIdx.x) {
                #pragma unroll
                for (int nj = 0; nj < 8; nj++) {
                    const int c0col = j0 + nj * 8 + (lane & 3) * 2;
                    if (c0col > r0)     s[nj][0] = -INFINITY;
                    if (c0col + 1 > r0) s[nj][1] = -INFINITY;
                    if (c0col > r1)     s[nj][2] = -INFINITY;
                    if (c0col + 1 > r1) s[nj][3] = -INFINITY;
                }
            }

            // ---- online softmax ----
            float t0 = -INFINITY, t1 = -INFINITY;
            #pragma unroll
            for (int nj = 0; nj < 8; nj++) {
                t0 = fmaxf(t0, fmaxf(s[nj][0], s[nj][1]));
                t1 = fmaxf(t1, fmaxf(s[nj][2], s[nj][3]));
            }
            t0 = fmaxf(t0, __shfl_xor_sync(0xffffffffu, t0, 1));
            t0 = fmaxf(t0, __shfl_xor_sync(0xffffffffu, t0, 2));
            t1 = fmaxf(t1, __shfl_xor_sync(0xffffffffu, t1, 1));
            t1 = fmaxf(t1, __shfl_xor_sync(0xffffffffu, t1, 2));
            const float mn0 = fmaxf(m0, t0);
            const float mn1 = fmaxf(m1, t1);
            const float a0 = __expf(m0 - mn0);
            const float a1 = __expf(m1 - mn1);

            float sum0 = 0.f, sum1 = 0.f;
            uint32_t pah[4][4], pal[4][4];
            #pragma unroll
            for (int kk = 0; kk < 4; kk++) {
                float p00 = __expf(s[2*kk][0]   - mn0), p01 = __expf(s[2*kk][1]   - mn0);
                float p02 = __expf(s[2*kk][2]   - mn1), p03 = __expf(s[2*kk][3]   - mn1);
                float p10 = __expf(s[2*kk+1][0] - mn0), p11 = __expf(s[2*kk+1][1] - mn0);
                float p12 = __expf(s[2*kk+1][2] - mn1), p13 = __expf(s[2*kk+1][3] - mn1);
                sum0 += p00 + p01 + p10 + p11;
                sum1 += p02 + p03 + p12 + p13;
                pah[kk][0] = packh_u32(p00, p01); pal[kk][0] = packl_u32(p00, p01, pah[kk][0]);
                pah[kk][1] = packh_u32(p02, p03); pal[kk][1] = packl_u32(p02, p03, pah[kk][1]);
                pah[kk][2] = packh_u32(p10, p11); pal[kk][2] = packl_u32(p10, p11, pah[kk][2]);
                pah[kk][3] = packh_u32(p12, p13); pal[kk][3] = packl_u32(p12, p13, pah[kk][3]);
            }
            l0 = l0 * a0 + sum0;
            l1 = l1 * a1 + sum1;
            #pragma unroll
            for (int nb = 0; nb < 8; nb++) {
                o[nb][0] *= a0; o[nb][1] *= a0;
                o[nb][2] *= a1; o[nb][3] *= a1;
            }

            // ---- O += P V (P split hi/lo, V single) ----
            #pragma unroll
            for (int kk = 0; kk < 4; kk++) {
                #pragma unroll
                for (int nbp = 0; nbp < 4; nbp++) {
                    const uint32_t addr = sV + (kk * 16 + (lane & 15)) * ATT_ROWB
                                        + nbp * 32 + (lane >> 4) * 16;
                    uint32_t f0, f1, f2, f3;
                    LDSM4T(f0, f1, f2, f3, addr);
                    uint32_t v0[2] = {f0, f1}, v1[2] = {f2, f3};
                    mma_fp16(o[2*nbp],   pah[kk], v0);
                    mma_fp16(o[2*nbp],   pal[kk], v0);
                    mma_fp16(o[2*nbp+1], pah[kk], v1);
                    mma_fp16(o[2*nbp+1], pal[kk], v1);
                }
            }
            m0 = mn0; m1 = mn1;
        }
        __syncthreads();
    }

    // ---- epilogue ----
    l0 += __shfl_xor_sync(0xffffffffu, l0, 1);
    l0 += __shfl_xor_sync(0xffffffffu, l0, 2);
    l1 += __shfl_xor_sync(0xffffffffu, l1, 1);
    l1 += __shfl_xor_sync(0xffffffffu, l1, 2);
    const float inv0 = 1.f / l0;
    const float inv1 = 1.f / l1;
    const size_t ro0 = ((size_t)b * SEQ + r0) * DMODEL + h * DHEAD;
    const size_t ro1 = ((size_t)b * SEQ + r1) * DMODEL + h * DHEAD;
    #pragma unroll
    for (int nb = 0; nb < 8; nb++) {
        const int dh = nb * 8 + (lane & 3) * 2;
        *(__half2*)(Og + ro0 + dh) = __floats2half2_rn(o[nb][0] * inv0, o[nb][1] * inv0);
        *(__half2*)(Og + ro1 + dh) = __floats2half2_rn(o[nb][2] * inv1, o[nb][3] * inv1);
    }
}

// ===========================================================================
// Launch
// ===========================================================================
extern "C" void kernel_launch(void* const* d_in, const int* in_sizes, int n_in,
                              void* d_out, int out_size)
{
    const float* x  = (const float*)d_in[0];
    const float* Wq = (const float*)d_in[1];
    const float* bq = (const float*)d_in[2];
    const float* Wk = (const float*)d_in[3];
    const float* bk = (const float*)d_in[4];
    const float* Wv = (const float*)d_in[5];
    const float* bv = (const float*)d_in[6];
    const float* Wo = (const float*)d_in[7];
    const float* bo = (const float*)d_in[8];
    const float* W1 = (const float*)d_in[9];
    const float* b1 = (const float*)d_in[10];
    const float* W2 = (const float*)d_in[11];
    const float* b2 = (const float*)d_in[12];
    float* out = (float*)d_out;

    __half *xh, *wqkv, *wo, *w1, *w2;
    __half *att, *x1h, *hh, *qp, *kp, *vp;
    float *px1;
    cudaGetSymbolAddress((void**)&xh, g_x);
    cudaGetSymbolAddress((void**)&wqkv, g_wqkv);   cudaGetSymbolAddress((void**)&wo, g_wo);
    cudaGetSymbolAddress((void**)&w1, g_w1);       cudaGetSymbolAddress((void**)&w2, g_w2);
    cudaGetSymbolAddress((void**)&att, g_att);
    cudaGetSymbolAddress((void**)&x1h, g_x1h);     cudaGetSymbolAddress((void**)&hh, g_h);
    cudaGetSymbolAddress((void**)&qp, g_q);        cudaGetSymbolAddress((void**)&kp, g_k);
    cudaGetSymbolAddress((void**)&vp, g_v);        cudaGetSymbolAddress((void**)&px1, g_x1);

    cudaFuncSetAttribute(tc_gemm<0>, cudaFuncAttributeMaxDynamicSharedMemorySize, GEMM_SMEM);
    cudaFuncSetAttribute(tc_gemm<1>, cudaFuncAttributeMaxDynamicSharedMemorySize, GEMM_SMEM);
    cudaFuncSetAttribute(tc_gemm<2>, cudaFuncAttributeMaxDynamicSharedMemorySize, GEMM_SMEM);
    cudaFuncSetAttribute(tc_gemm<3>, cudaFuncAttributeMaxDynamicSharedMemorySize, GEMM_SMEM);
    cudaFuncSetAttribute(flash_attn_tc, cudaFuncAttributeMaxDynamicSharedMemorySize, ATT_SMEM);

    const int T = 256;

    // (1) x + weights -> fp16
    round_all<<<(16*DMODEL*DMODEL/4 + T-1)/T, T>>>(x, Wq, Wk, Wv, Wo, W1, W2,
                                                   xh, wqkv, wo, w1, w2);

    const dim3 blk(512);

    // (2) QKV combined -> q (scaled), k, v  [B,H,S,Dh]
    tc_gemm<0><<<dim3(3*DMODEL/256, ROWS/128), blk, GEMM_SMEM>>>(
        xh, wqkv, bq, bk, bv, nullptr,
        nullptr, qp, kp, vp, ROWS, 3*DMODEL, DMODEL);

    // (3) tensor-core causal attention -> att fp16
    flash_attn_tc<<<dim3(SEQ/128, BATCH*HEADS), 256, ATT_SMEM>>>(qp, kp, vp, att);

    // (4) x1 = att*Wo^T + bo + x  (fp32 + fp16)
    tc_gemm<1><<<dim3(DMODEL/256, ROWS/128), blk, GEMM_SMEM>>>(
        att, wo, bo, nullptr, nullptr, x,
        px1, x1h, nullptr, nullptr, ROWS, DMODEL, DMODEL);

    // (5) h = relu(x1*W1^T + b1)  (fp16)
    tc_gemm<2><<<dim3(FFDIM/256, ROWS/128), blk, GEMM_SMEM>>>(
        x1h, w1, b1, nullptr, nullptr, nullptr,
        nullptr, hh, nullptr, nullptr, ROWS, FFDIM, DMODEL);

    // (6) out = h*W2^T + b2 + x1  (fp32)   <- ncu -s 5 -c 1 captures this
    tc_gemm<3><<<dim3(DMODEL/256, ROWS/128), blk, GEMM_SMEM>>>(
        hh, w2, b2, nullptr, nullptr, px1,
        out, nullptr, nullptr, nullptr, ROWS, DMODEL, FFDIM);
}

// round 9
// speedup vs baseline: 6.3881x; 1.1625x over previous
#include <cuda_runtime.h>
#include <cuda_fp16.h>
#include <cstdint>

// Problem constants
#define BATCH 2
#define SEQ   2048
#define DMODEL 1024
#define HEADS 16
#define DHEAD 64
#define FFDIM 4096
#define ROWS  (BATCH*SEQ)   // 4096

// ===========================================================================
// Scratch (allocation-free: __device__ globals)
// ===========================================================================
__device__ __half g_x[ROWS*DMODEL];
__device__ __half g_wqkv[3*DMODEL*DMODEL];
__device__ __half g_wo[DMODEL*DMODEL];
__device__ __half g_w1[FFDIM*DMODEL];
__device__ __half g_w2[DMODEL*FFDIM];
__device__ __half g_q[BATCH*HEADS*SEQ*DHEAD];
__device__ __half g_k[BATCH*HEADS*SEQ*DHEAD];
__device__ __half g_v[BATCH*HEADS*SEQ*DHEAD];
__device__ __half g_att[ROWS*DMODEL];
__device__ float  g_x1[ROWS*DMODEL];
__device__ __half g_x1h[ROWS*DMODEL];
__device__ __half g_h[ROWS*FFDIM];

// ===========================================================================
// Helpers
// ===========================================================================
__device__ __forceinline__ uint32_t smem_u32(const void* p) {
    uint32_t a;
    asm("{ .reg .u64 t; cvta.to.shared.u64 t, %1; cvt.u32.u64 %0, t; }" : "=r"(a) : "l"(p));
    return a;
}
#define CP_ASYNC16(dst_u32, src_ptr) \
    asm volatile("cp.async.cg.shared.global [%0], [%1], 16;" :: "r"(dst_u32), "l"(src_ptr) : "memory")
#define CP_COMMIT() asm volatile("cp.async.commit_group;" ::: "memory")
#define CP_WAIT0()  asm volatile("cp.async.wait_group 0;" ::: "memory")
#define CP_WAIT1()  asm volatile("cp.async.wait_group 1;" ::: "memory")
#define CP_WAIT2()  asm volatile("cp.async.wait_group 2;" ::: "memory")
#define LDSM4(r0,r1,r2,r3,addr) \
    asm volatile("ldmatrix.sync.aligned.m8n8.x4.shared.b16 {%0,%1,%2,%3}, [%4];" \
        : "=r"(r0), "=r"(r1), "=r"(r2), "=r"(r3) : "r"(addr))
#define LDSM4T(r0,r1,r2,r3,addr) \
    asm volatile("ldmatrix.sync.aligned.m8n8.x4.trans.shared.b16 {%0,%1,%2,%3}, [%4];" \
        : "=r"(r0), "=r"(r1), "=r"(r2), "=r"(r3) : "r"(addr))
__device__ __forceinline__ void mma_fp16(float* d, const uint32_t* a, const uint32_t* b) {
    asm volatile("mma.sync.aligned.m16n8k16.row.col.f32.f16.f16.f32 "
        "{%0,%1,%2,%3}, {%4,%5,%6,%7}, {%8,%9}, {%0,%1,%2,%3};"
        : "+f"(d[0]), "+f"(d[1]), "+f"(d[2]), "+f"(d[3])
        : "r"(a[0]), "r"(a[1]), "r"(a[2]), "r"(a[3]), "r"(b[0]), "r"(b[1]));
}
__device__ __forceinline__ uint32_t packh_u32(float a, float b) {
    __half2 p = __floats2half2_rn(a, b);
    return *reinterpret_cast<uint32_t*>(&p);
}
__device__ __forceinline__ uint32_t packl_u32(float a, float b, uint32_t hp_u32) {
    __half2 hp = *reinterpret_cast<__half2*>(&hp_u32);
    return packh_u32(a - __half2float(hp.x), b - __half2float(hp.y));
}

// ===========================================================================
// One rounding kernel: x + all weights -> fp16
// ===========================================================================
__global__ void round_all(const float* __restrict__ x,
                          const float* __restrict__ Wq, const float* __restrict__ Wk,
                          const float* __restrict__ Wv, const float* __restrict__ Wo,
                          const float* __restrict__ W1, const float* __restrict__ W2,
                          __half* __restrict__ xh, __half* __restrict__ wqkv,
                          __half* __restrict__ wo, __half* __restrict__ w1,
                          __half* __restrict__ w2) {
    const int S1 = DMODEL * DMODEL / 4;
    int i = blockIdx.x * blockDim.x + threadIdx.x;
    const float* src; __half* dst; int off;
    if      (i <  4*S1)  { src = x;  dst = xh;                      off = i; }
    else if (i <  5*S1)  { src = Wq; dst = wqkv;                    off = i - 4*S1; }
    else if (i <  6*S1)  { src = Wk; dst = wqkv + DMODEL*DMODEL;    off = i - 5*S1; }
    else if (i <  7*S1)  { src = Wv; dst = wqkv + 2*DMODEL*DMODEL;  off = i - 6*S1; }
    else if (i <  8*S1)  { src = Wo; dst = wo;                      off = i - 7*S1; }
    else if (i < 12*S1)  { src = W1; dst = w1;                      off = i - 8*S1; }
    else if (i < 16*S1)  { src = W2; dst = w2;                      off = i - 12*S1; }
    else return;
    float4 v = ((const float4*)src)[off];
    *(__half2*)(dst + (size_t)off * 4)     = __floats2half2_rn(v.x, v.y);
    *(__half2*)(dst + (size_t)off * 4 + 2) = __floats2half2_rn(v.z, v.w);
}

// ===========================================================================
// fp16 GEMM: C[M,N] = A[M,K] * W[N,K]^T + bias, epilogue by MODE:
//   MODE 0: QKV (N=3072) -> q (scaled 1/8), k, v  fp16 [B,H,S,Dh]
//   MODE 1: Wo: +res(x) -> x1 fp32 AND x1 fp16
//   MODE 2: FFN1: relu  -> h fp16
//   MODE 3: FFN2: +res(x1) -> out fp32
// 256 threads = 8 warps (2Mx4N); block 128x128; warp tile 64x32; BK=64;
// 3-stage cp.async; fragment double-buffering; 2 CTAs/SM.
// ===========================================================================
#define BK 64
#define ROWB 144                            // 64 halves = 128B + 16B pad
#define A_TILE (128 * ROWB)                 // 18432
#define W_TILE (128 * ROWB)                 // 18432
#define STAGE_B (A_TILE + W_TILE)           // 36864
#define NSTAGE 3
#define GEMM_SMEM (NSTAGE * STAGE_B)        // 110592

template<int MODE>
__global__ void __launch_bounds__(256, 2) tc_gemm(
    const __half* __restrict__ A, const __half* __restrict__ W,
    const float* __restrict__ bias0, const float* __restrict__ bias1, const float* __restrict__ bias2,
    const float* __restrict__ res,
    float* __restrict__ ofp,
    __half* __restrict__ o0, __half* __restrict__ o1, __half* __restrict__ o2,
    int M, int N, int K)
{
    extern __shared__ char smem[];
    const uint32_t sb = smem_u32(smem);
    const int tid = threadIdx.x;
    const int wid = tid >> 5;
    const int lane = tid & 31;
    const int wm = wid >> 2;            // 0..1
    const int wn = wid & 3;             // 0..3
    const int m0 = blockIdx.y * 128;
    const int n0 = blockIdx.x * 128;
    const int nc = K / BK;
    const int lr = lane & 15;
    const int lh = lane >> 4;

    auto load_chunk = [&](int c, int s) {
        const uint32_t stage = sb + s * STAGE_B;
        const int kbase = c * BK;
        #pragma unroll
        for (int i = 0; i < 8; i++) {
            const int u = tid + 256 * i;                 // 0..2047
            if (u < 1024) {                              // A tile 128x64
                const int r = u >> 3;
                const int kc = u & 7;
                CP_ASYNC16(stage + r * ROWB + kc * 16,
                           A + (size_t)(m0 + r) * K + kbase + kc * 8);
            } else {                                     // W tile 128x64
                const int v = u - 1024;
                const int r = v >> 3;
                const int kc = v & 7;
                CP_ASYNC16(stage + A_TILE + r * ROWB + kc * 16,
                           W + (size_t)(n0 + r) * K + kbase + kc * 8);
            }
        }
    };

    float d[4][4][4];
    #pragma unroll
    for (int i = 0; i < 4; i++)
        #pragma unroll
        for (int j = 0; j < 4; j++)
            #pragma unroll
            for (int e = 0; e < 4; e++) d[i][j][e] = 0.f;

    load_chunk(0, 0); CP_COMMIT();
    load_chunk(1, 1); CP_COMMIT();

    uint32_t ah[2][4][4];
    uint32_t wf[2][4][2];

    for (int c = 0; c < nc; c++) {
        if (c + 2 < nc) load_chunk(c + 2, (c + 2) % NSTAGE);
        CP_COMMIT();
        CP_WAIT2();
        __syncthreads();

        const uint32_t stage = sb + (c % NSTAGE) * STAGE_B;
        const uint32_t sA = stage;
        const uint32_t sW = stage + A_TILE;

        // fragment pipeline over 4 k-slices of 16
        #pragma unroll
        for (int mi = 0; mi < 4; mi++)
            LDSM4(ah[0][mi][0], ah[0][mi][1], ah[0][mi][2], ah[0][mi][3],
                  sA + (wm * 64 + mi * 16 + lr) * ROWB + lh * 16);
        #pragma unroll
        for (int p = 0; p < 2; p++) {
            uint32_t r0, r1, r2, r3;
            LDSM4(r0, r1, r2, r3, sW + (wn * 32 + p * 16 + lr) * ROWB + lh * 16);
            wf[0][2*p][0] = r0; wf[0][2*p][1] = r2;
            wf[0][2*p+1][0] = r1; wf[0][2*p+1][1] = r3;
        }

        #pragma unroll
        for (int kk = 0; kk < 4; kk++) {
            const int cur = kk & 1;
            if (kk < 3) {
                const int nxt = cur ^ 1;
                const uint32_t colb = (kk + 1) * 32 + lh * 16;
                #pragma unroll
                for (int mi = 0; mi < 4; mi++)
                    LDSM4(ah[nxt][mi][0], ah[nxt][mi][1], ah[nxt][mi][2], ah[nxt][mi][3],
                          sA + (wm * 64 + mi * 16 + lr) * ROWB + colb);
                #pragma unroll
                for (int p = 0; p < 2; p++) {
                    uint32_t r0, r1, r2, r3;
                    LDSM4(r0, r1, r2, r3, sW + (wn * 32 + p * 16 + lr) * ROWB + colb);
                    wf[nxt][2*p][0] = r0; wf[nxt][2*p][1] = r2;
                    wf[nxt][2*p+1][0] = r1; wf[nxt][2*p+1][1] = r3;
                }
            }
            #pragma unroll
            for (int mi = 0; mi < 4; mi++)
                #pragma unroll
                for (int nj = 0; nj < 4; nj++)
                    mma_fp16(d[mi][nj], ah[cur][mi], wf[cur][nj]);
        }
        __syncthreads();
    }

    const int g = lane >> 2;
    const int t2 = (lane & 3) * 2;

    #pragma unroll
    for (int mi = 0; mi < 4; mi++) {
        const int m = m0 + wm * 64 + mi * 16 + g;
        #pragma unroll
        for (int nj = 0; nj < 4; nj++) {
            const int n = n0 + wn * 32 + nj * 8 + t2;
            float c0 = d[mi][nj][0], c1 = d[mi][nj][1];
            float c2 = d[mi][nj][2], c3 = d[mi][nj][3];

            if (MODE == 0) {
                const int which = n >> 10;               // uniform per CTA
                const int nn = n & 1023;
                const float* bp = (which == 0) ? bias0 : (which == 1) ? bias1 : bias2;
                const float sc = (which == 0) ? 0.125f : 1.0f;
                const float bx = bp[nn], by = bp[nn + 1];
                __half* dst = (which == 0) ? o0 : (which == 1) ? o1 : o2;
                const int h = nn >> 6, dh = nn & 63;
                const int b = m >> 11, s_ = m & 2047;
                const size_t i0 = (((size_t)b * HEADS + h) * SEQ + s_) * DHEAD + dh;
                const size_t i1 = (((size_t)b * HEADS + h) * SEQ + s_ + 8) * DHEAD + dh;
                *(__half2*)(dst + i0) = __floats2half2_rn((c0 + bx) * sc, (c1 + by) * sc);
                *(__half2*)(dst + i1) = __floats2half2_rn((c2 + bx) * sc, (c3 + by) * sc);
            } else {
                const float bx = bias0[n], by = bias0[n + 1];
                const size_t i0 = (size_t)m * N + n;
                const size_t i1 = (size_t)(m + 8) * N + n;
                float v00 = c0 + bx, v01 = c1 + by;
                float v10 = c2 + bx, v11 = c3 + by;
                if (MODE == 1 || MODE == 3) {
                    const float2 r0 = *(const float2*)(res + i0);
                    const float2 r1 = *(const float2*)(res + i1);
                    v00 += r0.x; v01 += r0.y; v10 += r1.x; v11 += r1.y;
                }
                if (MODE == 2) {
                    v00 = fmaxf(v00, 0.f); v01 = fmaxf(v01, 0.f);
                    v10 = fmaxf(v10, 0.f); v11 = fmaxf(v11, 0.f);
                }
                if (MODE == 1 || MODE == 3) {
                    *(float2*)(ofp + i0) = make_float2(v00, v01);
                    *(float2*)(ofp + i1) = make_float2(v10, v11);
                }
                if (MODE == 1 || MODE == 2) {
                    *(__half2*)(o0 + i0) = __floats2half2_rn(v00, v01);
                    *(__half2*)(o0 + i1) = __floats2half2_rn(v10, v11);
                }
            }
        }
    }
}

// ===========================================================================
// Tensor-core causal flash attention (unchanged from R7).
// Q single fp16 (pre-scaled 1/8) -> 1-product QK^T; P split hi/lo -> 2-product PV.
// ===========================================================================
#define ATT_ROWB 144
#define ATT_QTILE (128*ATT_ROWB)
#define ATT_KV_TILE (64*ATT_ROWB)
#define ATT_STAGE (2*ATT_KV_TILE)
#define ATT_SMEM (ATT_QTILE + 2*ATT_STAGE)    // 55296

__global__ void __launch_bounds__(256, 1) flash_attn_tc(
    const __half* __restrict__ Qg,
    const __half* __restrict__ Kg, const __half* __restrict__ Vg,
    __half* __restrict__ Og)
{
    extern __shared__ char smem[];
    const uint32_t sb = smem_u32(smem);
    const int tid = threadIdx.x;
    const int wid = tid >> 5;
    const int lane = tid & 31;
    const int bh = blockIdx.y;
    const int b  = bh >> 4;
    const int h  = bh & 15;
    const int q0 = blockIdx.x * 128;
    const size_t base = (size_t)bh * SEQ * DHEAD;

    const uint32_t sQ  = sb;
    const uint32_t sKV = sb + ATT_QTILE;

    #pragma unroll
    for (int i = 0; i < 4; i++) {
        const int u = tid + 256 * i;
        const int r = u >> 3, c = u & 7;
        CP_ASYNC16(sQ + r * ATT_ROWB + c * 16, Qg + base + (size_t)(q0 + r) * DHEAD + c * 8);
    }
    CP_COMMIT();

    auto load_kv = [&](int t, int s) {
        const uint32_t stage = sKV + s * ATT_STAGE;
        const int j0 = t * 64;
        #pragma unroll
        for (int i = 0; i < 4; i++) {
            const int u = tid + 256 * i;
            const int tile = u >> 9;
            const int w = u & 511;
            const int r = w >> 3, c = w & 7;
            const uint32_t dst = stage + tile * ATT_KV_TILE + r * ATT_ROWB + c * 16;
            const __half* src = (tile == 0 ? Kg : Vg) + base + (size_t)(j0 + r) * DHEAD + c * 8;
            CP_ASYNC16(dst, src);
        }
    };

    load_kv(0, 0); CP_COMMIT();
    CP_WAIT0();
    __syncthreads();

    uint32_t qf[4][4];
    #pragma unroll
    for (int kd = 0; kd < 4; kd++) {
        const uint32_t addr = sQ + (wid * 16 + (lane & 15)) * ATT_ROWB
                            + kd * 32 + (lane >> 4) * 16;
        LDSM4(qf[kd][0], qf[kd][1], qf[kd][2], qf[kd][3], addr);
    }

    float m0 = -INFINITY, m1 = -INFINITY, l0 = 0.f, l1 = 0.f;
    float o[8][4];
    #pragma unroll
    for (int nb = 0; nb < 8; nb++)
        #pragma unroll
        for (int e = 0; e < 4; e++) o[nb][e] = 0.f;

    const int numT = 2 * blockIdx.x + 2;
    const int r0 = q0 + wid * 16 + (lane >> 2);
    const int r1 = r0 + 8;

    for (int t = 0; t < numT; t++) {
        const int j0 = t * 64;
        if (t + 1 < numT) load_kv(t + 1, (t + 1) & 1);
        CP_COMMIT();
        CP_WAIT1();
        __syncthreads();

        if (j0 <= q0 + wid * 16 + 15) {
            const uint32_t sK = sKV + (t & 1) * ATT_STAGE;
            const uint32_t sV = sK + ATT_KV_TILE;

            float s[8][4];
            #pragma unroll
            for (int nj = 0; nj < 8; nj++)
                #pragma unroll
                for (int e = 0; e < 4; e++) s[nj][e] = 0.f;

            #pragma unroll
            for (int kd = 0; kd < 4; kd++) {
                #pragma unroll
                for (int sjp = 0; sjp < 4; sjp++) {
                    const uint32_t addr = sK + (sjp * 16 + (lane & 15)) * ATT_ROWB
                                        + kd * 32 + (lane >> 4) * 16;
                    uint32_t f0, f1, f2, f3;
                    LDSM4(f0, f1, f2, f3, addr);
                    uint32_t b0[2] = {f0, f2}, b1[2] = {f1, f3};
                    mma_fp16(s[2*sjp],   qf[kd], b0);
                    mma_fp16(s[2*sjp+1], qf[kd], b1);
                }
            }

            if (t >= 2 * blockIdx.x) {
                #pragma unroll
                for (int nj = 0; nj < 8; nj++) {
                    const int c0col = j0 + nj * 8 + (lane & 3) * 2;
                    if (c0col > r0)     s[nj][0] = -INFINITY;
                    if (c0col + 1 > r0) s[nj][1] = -INFINITY;
                    if (c0col > r1)     s[nj][2] = -INFINITY;
                    if (c0col + 1 > r1) s[nj][3] = -INFINITY;
                }
            }

            float t0 = -INFINITY, t1 = -INFINITY;
            #pragma unroll
            for (int nj = 0; nj < 8; nj++) {
                t0 = fmaxf(t0, fmaxf(s[nj][0], s[nj][1]));
                t1 = fmaxf(t1, fmaxf(s[nj][2], s[nj][3]));
            }
            t0 = fmaxf(t0, __shfl_xor_sync(0xffffffffu, t0, 1));
            t0 = fmaxf(t0, __shfl_xor_sync(0xffffffffu, t0, 2));
            t1 = fmaxf(t1, __shfl_xor_sync(0xffffffffu, t1, 1));
            t1 = fmaxf(t1, __shfl_xor_sync(0xffffffffu, t1, 2));
            const float mn0 = fmaxf(m0, t0);
            const float mn1 = fmaxf(m1, t1);
            const float a0 = __expf(m0 - mn0);
            const float a1 = __expf(m1 - mn1);

            float sum0 = 0.f, sum1 = 0.f;
            uint32_t pah[4][4], pal[4][4];
            #pragma unroll
            for (int kk = 0; kk < 4; kk++) {
                float p00 = __expf(s[2*kk][0]   - mn0), p01 = __expf(s[2*kk][1]   - mn0);
                float p02 = __expf(s[2*kk][2]   - mn1), p03 = __expf(s[2*kk][3]   - mn1);
                float p10 = __expf(s[2*kk+1][0] - mn0), p11 = __expf(s[2*kk+1][1] - mn0);
                float p12 = __expf(s[2*kk+1][2] - mn1), p13 = __expf(s[2*kk+1][3] - mn1);
                sum0 += p00 + p01 + p10 + p11;
                sum1 += p02 + p03 + p12 + p13;
                pah[kk][0] = packh_u32(p00, p01); pal[kk][0] = packl_u32(p00, p01, pah[kk][0]);
                pah[kk][1] = packh_u32(p02, p03); pal[kk][1] = packl_u32(p02, p03, pah[kk][1]);
                pah[kk][2] = packh_u32(p10, p11); pal[kk][2] = packl_u32(p10, p11, pah[kk][2]);
                pah[kk][3] = packh_u32(p12, p13); pal[kk][3] = packl_u32(p12, p13, pah[kk][3]);
            }
            l0 = l0 * a0 + sum0;
            l1 = l1 * a1 + sum1;
            #pragma unroll
            for (int nb = 0; nb < 8; nb++) {
                o[nb][0] *= a0; o[nb][1] *= a0;
                o[nb][2] *= a1; o[nb][3] *= a1;
            }

            #pragma unroll
            for (int kk = 0; kk < 4; kk++) {
                #pragma unroll
                for (int nbp = 0; nbp < 4; nbp++) {
                    const uint32_t addr = sV + (kk * 16 + (lane & 15)) * ATT_ROWB
                                        + nbp * 32 + (lane >> 4) * 16;
                    uint32_t f0, f1, f2, f3;
                    LDSM4T(f0, f1, f2, f3, addr);
                    uint32_t v0[2] = {f0, f1}, v1[2] = {f2, f3};
                    mma_fp16(o[2*nbp],   pah[kk], v0);
                    mma_fp16(o[2*nbp],   pal[kk], v0);
                    mma_fp16(o[2*nbp+1], pah[kk], v1);
                    mma_fp16(o[2*nbp+1], pal[kk], v1);
                }
            }
            m0 = mn0; m1 = mn1;
        }
        __syncthreads();
    }

    l0 += __shfl_xor_sync(0xffffffffu, l0, 1);
    l0 += __shfl_xor_sync(0xffffffffu, l0, 2);
    l1 += __shfl_xor_sync(0xffffffffu, l1, 1);
    l1 += __shfl_xor_sync(0xffffffffu, l1, 2);
    const float inv0 = 1.f / l0;
    const float inv1 = 1.f / l1;
    const size_t ro0 = ((size_t)b * SEQ + r0) * DMODEL + h * DHEAD;
    const size_t ro1 = ((size_t)b * SEQ + r1) * DMODEL + h * DHEAD;
    #pragma unroll
    for (int nb = 0; nb < 8; nb++) {
        const int dh = nb * 8 + (lane & 3) * 2;
        *(__half2*)(Og + ro0 + dh) = __floats2half2_rn(o[nb][0] * inv0, o[nb][1] * inv0);
        *(__half2*)(Og + ro1 + dh) = __floats2half2_rn(o[nb][2] * inv1, o[nb][3] * inv1);
    }
}

// ===========================================================================
// Launch
// ===========================================================================
extern "C" void kernel_launch(void* const* d_in, const int* in_sizes, int n_in,
                              void* d_out, int out_size)
{
    const float* x  = (const float*)d_in[0];
    const float* Wq = (const float*)d_in[1];
    const float* bq = (const float*)d_in[2];
    const float* Wk = (const float*)d_in[3];
    const float* bk = (const float*)d_in[4];
    const float* Wv = (const float*)d_in[5];
    const float* bv = (const float*)d_in[6];
    const float* Wo = (const float*)d_in[7];
    const float* bo = (const float*)d_in[8];
    const float* W1 = (const float*)d_in[9];
    const float* b1 = (const float*)d_in[10];
    const float* W2 = (const float*)d_in[11];
    const float* b2 = (const float*)d_in[12];
    float* out = (float*)d_out;

    __half *xh, *wqkv, *wo, *w1, *w2;
    __half *att, *x1h, *hh, *qp, *kp, *vp;
    float *px1;
    cudaGetSymbolAddress((void**)&xh, g_x);
    cudaGetSymbolAddress((void**)&wqkv, g_wqkv);   cudaGetSymbolAddress((void**)&wo, g_wo);
    cudaGetSymbolAddress((void**)&w1, g_w1);       cudaGetSymbolAddress((void**)&w2, g_w2);
    cudaGetSymbolAddress((void**)&att, g_att);
    cudaGetSymbolAddress((void**)&x1h, g_x1h);     cudaGetSymbolAddress((void**)&hh, g_h);
    cudaGetSymbolAddress((void**)&qp, g_q);        cudaGetSymbolAddress((void**)&kp, g_k);
    cudaGetSymbolAddress((void**)&vp, g_v);        cudaGetSymbolAddress((void**)&px1, g_x1);

    cudaFuncSetAttribute(tc_gemm<0>, cudaFuncAttributeMaxDynamicSharedMemorySize, GEMM_SMEM);
    cudaFuncSetAttribute(tc_gemm<1>, cudaFuncAttributeMaxDynamicSharedMemorySize, GEMM_SMEM);
    cudaFuncSetAttribute(tc_gemm<2>, cudaFuncAttributeMaxDynamicSharedMemorySize, GEMM_SMEM);
    cudaFuncSetAttribute(tc_gemm<3>, cudaFuncAttributeMaxDynamicSharedMemorySize, GEMM_SMEM);
    cudaFuncSetAttribute(flash_attn_tc, cudaFuncAttributeMaxDynamicSharedMemorySize, ATT_SMEM);

    const int T = 256;

    // (1) x + weights -> fp16
    round_all<<<(16*DMODEL*DMODEL/4 + T-1)/T, T>>>(x, Wq, Wk, Wv, Wo, W1, W2,
                                                   xh, wqkv, wo, w1, w2);

    const dim3 blk(256);

    // (2) QKV combined -> q (scaled), k, v  [B,H,S,Dh]
    tc_gemm<0><<<dim3(3*DMODEL/128, ROWS/128), blk, GEMM_SMEM>>>(
        xh, wqkv, bq, bk, bv, nullptr,
        nullptr, qp, kp, vp, ROWS, 3*DMODEL, DMODEL);

    // (3) tensor-core causal attention -> att fp16
    flash_attn_tc<<<dim3(SEQ/128, BATCH*HEADS), 256, ATT_SMEM>>>(qp, kp, vp, att);

    // (4) x1 = att*Wo^T + bo + x  (fp32 + fp16)
    tc_gemm<1><<<dim3(DMODEL/128, ROWS/128), blk, GEMM_SMEM>>>(
        att, wo, bo, nullptr, nullptr, x,
        px1, x1h, nullptr, nullptr, ROWS, DMODEL, DMODEL);

    // (5) h = relu(x1*W1^T + b1)  (fp16)
    tc_gemm<2><<<dim3(FFDIM/128, ROWS/128), blk, GEMM_SMEM>>>(
        x1h, w1, b1, nullptr, nullptr, nullptr,
        nullptr, hh, nullptr, nullptr, ROWS, FFDIM, DMODEL);

    // (6) out = h*W2^T + b2 + x1  (fp32)
    tc_gemm<3><<<dim3(DMODEL/128, ROWS/128), blk, GEMM_SMEM>>>(
        hh, w2, b2, nullptr, nullptr, px1,
        out, nullptr, nullptr, nullptr, ROWS, DMODEL, FFDIM);
}